// round 9
// baseline (speedup 1.0000x reference)
#include <cuda_runtime.h>
#include <cuda_fp16.h>
#include <cstdint>

#define K_CODES 8192
#define C_DIM   64
#define N_TOK   16384
#define HW      1024
#define TPB     256
#define MTILE   128                  // tokens per CTA
#define NTILE   64                   // codes per tile
#define NTILES  (K_CODES / NTILE)    // 128
#define MARGIN1 0.1f
#define MARGIN2 1e-4f

// output layout (float32, concatenated in reference return order)
#define O_ZQST 0
#define O_IDX  1048576
#define O_ZQ   1064960
#define O_EMB  2113536
#define O_CS   2637824
#define O_AVG  2646016

// smem layout for k_dist1 (1 comp)
#define SM1_A   0                        // 128 rows x 128B = 16384
#define SM1_B   16384                    // 2 bufs x 8192
#define SM1_HN  32768                    // 2 x 256B
#define SMEM1_TOTAL (32768 + 512 + 128)

// smem layout for k_dist2 (2 comps)
#define SM_A    0                        // 2 comps x 128 rows x 128B = 32768
#define SM_B    32768                    // 2 bufs x 2 comps x 8192 = 32768
#define SM_HN   65536                    // 2 x 256B
#define SMEM2_TOTAL (65536 + 512 + 128)

typedef unsigned long long u64;
typedef unsigned int u32;

static __device__ __half g_Eh[K_CODES * C_DIM];
static __device__ __half g_Er[K_CODES * C_DIM];
static __device__ float g_hn[K_CODES];
static __device__ int   g_idx[N_TOK];
static __device__ int   g_flag2[N_TOK];
static __device__ u64   g_key[N_TOK];
static __device__ int   g_list[N_TOK];
static __device__ int   g_list2[N_TOK];
static __device__ int   g_nflag;
static __device__ int   g_nflag2;
static __device__ float g_counts[K_CODES];
static __device__ float g_dw[K_CODES * C_DIM];
static __device__ float g_n;

// ---------------------------------------------------------------- helpers
__device__ __forceinline__ uint32_t smem_u32(const void* p) {
    uint32_t a;
    asm("{ .reg .u64 t; cvta.to.shared.u64 t, %1; cvt.u32.u64 %0, t; }"
        : "=r"(a) : "l"(p));
    return a;
}
__device__ __forceinline__ void cp_async16(uint32_t saddr, const void* gmem) {
    asm volatile("cp.async.cg.shared.global [%0], [%1], 16;\n" :: "r"(saddr), "l"(gmem));
}
#define CP_COMMIT() asm volatile("cp.async.commit_group;\n" ::: "memory")
#define CP_WAIT(n)  asm volatile("cp.async.wait_group %0;\n" :: "n"(n) : "memory")

__device__ __forceinline__ uint32_t sw128(uint32_t off) {
    return off ^ ((off >> 3) & 0x70);
}
__device__ __forceinline__ void ldsm4(u32& r0, u32& r1, u32& r2, u32& r3, uint32_t addr) {
    asm volatile("ldmatrix.sync.aligned.m8n8.x4.shared.b16 {%0,%1,%2,%3}, [%4];"
                 : "=r"(r0), "=r"(r1), "=r"(r2), "=r"(r3) : "r"(addr));
}
__device__ __forceinline__ void mma16816(float& d0, float& d1, float& d2, float& d3,
                                         u32 a0, u32 a1, u32 a2, u32 a3,
                                         u32 b0, u32 b1) {
    asm volatile("mma.sync.aligned.m16n8k16.row.col.f32.f16.f16.f32 "
                 "{%0,%1,%2,%3}, {%4,%5,%6,%7}, {%8,%9}, {%0,%1,%2,%3};"
                 : "+f"(d0), "+f"(d1), "+f"(d2), "+f"(d3)
                 : "r"(a0), "r"(a1), "r"(a2), "r"(a3), "r"(b0), "r"(b1));
}
__device__ __forceinline__ u32 fmono(float s) {
    u32 u = __float_as_uint(s);
    return (s < 0.0f) ? ~u : (u | 0x80000000u);
}

// top-2 tracking helpers (max score; first index wins ties via strict >)
struct Top2 { float b1, b2; int i1; };
__device__ __forceinline__ void t2_push(Top2& t, float s, int idx) {
    if (s > t.b1) { t.b2 = t.b1; t.b1 = s; t.i1 = idx; }
    else if (s > t.b2) t.b2 = s;
}
__device__ __forceinline__ void t2_merge_shfl(Top2& t, int o) {
    float ob1 = __shfl_xor_sync(0xffffffffu, t.b1, o);
    float ob2 = __shfl_xor_sync(0xffffffffu, t.b2, o);
    int   oi1 = __shfl_xor_sync(0xffffffffu, t.i1, o);
    if (ob1 > t.b1 || (ob1 == t.b1 && oi1 < t.i1)) {
        t.b2 = fmaxf(t.b1, ob2); t.b1 = ob1; t.i1 = oi1;
    } else {
        t.b2 = fmaxf(t.b2, ob1);
    }
}

// ---------------------------------------------------------------------------
__global__ void k_init() {
    int i = blockIdx.x * blockDim.x + threadIdx.x;
    if (i < K_CODES) g_counts[i] = 0.0f;
    if (i < K_CODES * C_DIM) g_dw[i] = 0.0f;
    if (i < N_TOK) g_flag2[i] = 0;
    if (i == 0) { g_nflag = 0; g_nflag2 = 0; g_n = 0.0f; }
}

// split embedding into 2 fp16 components + half squared norms
__global__ void k_splitE(const float* __restrict__ emb) {
    int w = (blockIdx.x * blockDim.x + threadIdx.x) >> 5;
    int lane = threadIdx.x & 31;
    if (w >= K_CODES) return;
    float s = 0.0f;
    #pragma unroll
    for (int half = 0; half < 2; half++) {
        int c = lane + half * 32;
        float x = emb[w * C_DIM + c];
        s += x * x;
        __half h = __float2half_rn(x);
        float r = x - __half2float(h);
        g_Eh[w * C_DIM + c] = h;
        g_Er[w * C_DIM + c] = __float2half_rn(r);
    }
    #pragma unroll
    for (int o = 16; o > 0; o >>= 1) s += __shfl_xor_sync(0xffffffffu, s, o);
    if (lane == 0) g_hn[w] = 0.5f * s;
}

// ---------------------------------------------------------------------------
// STAGE 1: coarse scores, hh term only. Flags ambiguous tokens (gap < MARGIN1).
__global__ void __launch_bounds__(TPB, 1) k_dist1(const float* __restrict__ z) {
    extern __shared__ char smem[];
    const uint32_t sb = smem_u32(smem);
    const int tid = threadIdx.x;
    const int lane = tid & 31;
    const int w = tid >> 5;

    // --- load 128 tokens (h comp only) into sA ---
    {
        int r = tid & 127;
        int half = tid >> 7;
        int t = blockIdx.x * MTILE + r;
        const float* zp = z + (size_t)(t >> 10) * (C_DIM * HW) + (t & 1023);
        #pragma unroll
        for (int j = 0; j < 32; j++) {
            int c = half * 32 + j;
            uint32_t off = sw128((uint32_t)(r * 128 + c * 2));
            *(__half*)(smem + SM1_A + off) = __float2half_rn(zp[c * HW]);
        }
    }
    __syncthreads();

    // --- preload A fragments: 4 ksteps x 4 regs ---
    u32 afr[4][4];
    {
        int arow = w * 16 + (lane & 7) + ((lane >> 3) & 1) * 8;
        int akb  = (lane >> 4) * 16;
        #pragma unroll
        for (int q = 0; q < 4; q++) {
            uint32_t addr = sb + SM1_A + sw128((uint32_t)(arow * 128 + q * 32 + akb));
            ldsm4(afr[q][0], afr[q][1], afr[q][2], afr[q][3], addr);
        }
    }

    auto load_tile = [&](int tile, int bufi) {
        const char* src = (const char*)g_Eh + (size_t)tile * (NTILE * C_DIM * 2);
        uint32_t dst = sb + SM1_B + (uint32_t)bufi * 8192u;
        #pragma unroll
        for (int u = 0; u < 2; u++) {
            uint32_t off = (uint32_t)(u * TPB + tid) * 16u;
            cp_async16(dst + sw128(off), src + off);
        }
        if (tid < 16)
            cp_async16(sb + SM1_HN + bufi * 256 + tid * 16,
                       (const char*)(g_hn + tile * NTILE) + tid * 16);
    };

    const int brow = (lane & 7) + ((lane >> 4) & 1) * 8;
    const int bkb  = ((lane >> 3) & 1) * 16;

    Top2 t0 = {-3.4e38f, -3.4e38f, 0};
    Top2 t1 = {-3.4e38f, -3.4e38f, 0};

    load_tile(0, 0); CP_COMMIT();
    load_tile(1, 1); CP_COMMIT();

    for (int ci = 0; ci < NTILES; ci++) {
        const int buf = ci & 1;
        if (ci + 1 < NTILES) { CP_WAIT(1); } else { CP_WAIT(0); }
        __syncthreads();

        float acc[8][4];
        #pragma unroll
        for (int g = 0; g < 8; g++)
            #pragma unroll
            for (int v = 0; v < 4; v++) acc[g][v] = 0.0f;

        uint32_t bbase = sb + SM1_B + (uint32_t)buf * 8192u;
        #pragma unroll
        for (int q = 0; q < 4; q++) {
            u32 bfr[8][2];
            #pragma unroll
            for (int g2 = 0; g2 < 4; g2++) {
                uint32_t addr = bbase +
                    sw128((uint32_t)((g2 * 16 + brow) * 128 + q * 32 + bkb));
                ldsm4(bfr[2 * g2][0], bfr[2 * g2][1],
                      bfr[2 * g2 + 1][0], bfr[2 * g2 + 1][1], addr);
            }
            #pragma unroll
            for (int g = 0; g < 8; g++)
                mma16816(acc[g][0], acc[g][1], acc[g][2], acc[g][3],
                         afr[q][0], afr[q][1], afr[q][2], afr[q][3],
                         bfr[g][0], bfr[g][1]);
        }

        const float* hnp = (const float*)(smem + SM1_HN + buf * 256);
        const int colbase = ci * NTILE + 2 * (lane & 3);
        #pragma unroll
        for (int g = 0; g < 8; g++) {
            int lc = g * 8 + 2 * (lane & 3);
            float h0 = hnp[lc], h1 = hnp[lc + 1];
            int c0 = colbase + g * 8, c1 = c0 + 1;
            t2_push(t0, acc[g][0] - h0, c0);
            t2_push(t0, acc[g][1] - h1, c1);
            t2_push(t1, acc[g][2] - h0, c0);
            t2_push(t1, acc[g][3] - h1, c1);
        }

        __syncthreads();
        if (ci + 2 < NTILES) { load_tile(ci + 2, buf); CP_COMMIT(); }
    }

    #pragma unroll
    for (int o = 1; o <= 2; o <<= 1) { t2_merge_shfl(t0, o); t2_merge_shfl(t1, o); }

    if ((lane & 3) == 0) {
        int r = w * 16 + (lane >> 2);
        int tt = blockIdx.x * MTILE + r;
        g_idx[tt] = t0.i1;
        if (t0.b1 - t0.b2 < MARGIN1) {
            int slot = atomicAdd(&g_nflag, 1);
            g_list[slot] = tt;
        }
        g_idx[tt + 8] = t1.i1;
        if (t1.b1 - t1.b2 < MARGIN1) {
            int slot = atomicAdd(&g_nflag, 1);
            g_list[slot] = tt + 8;
        }
    }
}

// ---------------------------------------------------------------------------
// STAGE 2: accurate 3-term scores for flagged tokens (gathered tiles).
// Fixed 128-block grid; blocks beyond ceil(nf/128) exit.
__global__ void __launch_bounds__(TPB, 1) k_dist2(const float* __restrict__ z) {
    const int nf = g_nflag;
    if ((int)blockIdx.x * MTILE >= nf) return;

    extern __shared__ char smem[];
    const uint32_t sb = smem_u32(smem);
    const int tid = threadIdx.x;
    const int lane = tid & 31;
    const int w = tid >> 5;

    // --- gather 128 flagged tokens, 2-way fp16 split into sA ---
    {
        int r = tid & 127;
        int half = tid >> 7;
        int li = blockIdx.x * MTILE + r;
        int t = g_list[(li < nf) ? li : 0];
        const float* zp = z + (size_t)(t >> 10) * (C_DIM * HW) + (t & 1023);
        #pragma unroll
        for (int j = 0; j < 32; j++) {
            int c = half * 32 + j;
            float x = zp[c * HW];
            __half h = __float2half_rn(x);
            float rr = x - __half2float(h);
            uint32_t off = sw128((uint32_t)(r * 128 + c * 2));
            *(__half*)(smem + SM_A + off) = h;
            *(__half*)(smem + SM_A + 16384 + off) = __float2half_rn(rr);
        }
    }
    __syncthreads();

    u32 afr[2][4][4];
    {
        int arow = w * 16 + (lane & 7) + ((lane >> 3) & 1) * 8;
        int akb  = (lane >> 4) * 16;
        #pragma unroll
        for (int c = 0; c < 2; c++)
            #pragma unroll
            for (int q = 0; q < 4; q++) {
                uint32_t addr = sb + SM_A + c * 16384 +
                                sw128((uint32_t)(arow * 128 + q * 32 + akb));
                ldsm4(afr[c][q][0], afr[c][q][1], afr[c][q][2], afr[c][q][3], addr);
            }
    }

    auto load_tile = [&](int tile, int bufi) {
        const char* srcs[2] = {(const char*)g_Eh, (const char*)g_Er};
        #pragma unroll
        for (int c = 0; c < 2; c++) {
            const char* src = srcs[c] + (size_t)tile * (NTILE * C_DIM * 2);
            uint32_t dst = sb + SM_B + (uint32_t)(bufi * 2 + c) * 8192u;
            #pragma unroll
            for (int u = 0; u < 2; u++) {
                uint32_t off = (uint32_t)(u * TPB + tid) * 16u;
                cp_async16(dst + sw128(off), src + off);
            }
        }
        if (tid < 16)
            cp_async16(sb + SM_HN + bufi * 256 + tid * 16,
                       (const char*)(g_hn + tile * NTILE) + tid * 16);
    };

    const int brow = (lane & 7) + ((lane >> 4) & 1) * 8;
    const int bkb  = ((lane >> 3) & 1) * 16;

    Top2 t0 = {-3.4e38f, -3.4e38f, 0};
    Top2 t1 = {-3.4e38f, -3.4e38f, 0};

    load_tile(0, 0); CP_COMMIT();
    load_tile(1, 1); CP_COMMIT();

    for (int ci = 0; ci < NTILES; ci++) {
        const int buf = ci & 1;
        if (ci + 1 < NTILES) { CP_WAIT(1); } else { CP_WAIT(0); }
        __syncthreads();

        float acc[8][4];
        #pragma unroll
        for (int g = 0; g < 8; g++)
            #pragma unroll
            for (int v = 0; v < 4; v++) acc[g][v] = 0.0f;

        #pragma unroll
        for (int q = 0; q < 4; q++) {
            u32 bfr[8][2];
            uint32_t b0base = sb + SM_B + (uint32_t)(buf * 2) * 8192u;
            #pragma unroll
            for (int g2 = 0; g2 < 4; g2++) {
                uint32_t addr = b0base +
                    sw128((uint32_t)((g2 * 16 + brow) * 128 + q * 32 + bkb));
                ldsm4(bfr[2 * g2][0], bfr[2 * g2][1],
                      bfr[2 * g2 + 1][0], bfr[2 * g2 + 1][1], addr);
            }
            #pragma unroll
            for (int g = 0; g < 8; g++) {
                mma16816(acc[g][0], acc[g][1], acc[g][2], acc[g][3],
                         afr[0][q][0], afr[0][q][1], afr[0][q][2], afr[0][q][3],
                         bfr[g][0], bfr[g][1]);
                mma16816(acc[g][0], acc[g][1], acc[g][2], acc[g][3],
                         afr[1][q][0], afr[1][q][1], afr[1][q][2], afr[1][q][3],
                         bfr[g][0], bfr[g][1]);
            }
            uint32_t b1base = sb + SM_B + (uint32_t)(buf * 2 + 1) * 8192u;
            #pragma unroll
            for (int g2 = 0; g2 < 4; g2++) {
                uint32_t addr = b1base +
                    sw128((uint32_t)((g2 * 16 + brow) * 128 + q * 32 + bkb));
                ldsm4(bfr[2 * g2][0], bfr[2 * g2][1],
                      bfr[2 * g2 + 1][0], bfr[2 * g2 + 1][1], addr);
            }
            #pragma unroll
            for (int g = 0; g < 8; g++)
                mma16816(acc[g][0], acc[g][1], acc[g][2], acc[g][3],
                         afr[0][q][0], afr[0][q][1], afr[0][q][2], afr[0][q][3],
                         bfr[g][0], bfr[g][1]);
        }

        const float* hnp = (const float*)(smem + SM_HN + buf * 256);
        const int colbase = ci * NTILE + 2 * (lane & 3);
        #pragma unroll
        for (int g = 0; g < 8; g++) {
            int lc = g * 8 + 2 * (lane & 3);
            float h0 = hnp[lc], h1 = hnp[lc + 1];
            int c0 = colbase + g * 8, c1 = c0 + 1;
            t2_push(t0, acc[g][0] - h0, c0);
            t2_push(t0, acc[g][1] - h1, c1);
            t2_push(t1, acc[g][2] - h0, c0);
            t2_push(t1, acc[g][3] - h1, c1);
        }

        __syncthreads();
        if (ci + 2 < NTILES) { load_tile(ci + 2, buf); CP_COMMIT(); }
    }

    #pragma unroll
    for (int o = 1; o <= 2; o <<= 1) { t2_merge_shfl(t0, o); t2_merge_shfl(t1, o); }

    if ((lane & 3) == 0) {
        int r = w * 16 + (lane >> 2);
        #pragma unroll
        for (int pair = 0; pair < 2; pair++) {
            Top2& tp = pair ? t1 : t0;
            int li = blockIdx.x * MTILE + r + pair * 8;
            if (li < nf) {
                int tt = g_list[li];
                g_idx[tt] = tp.i1;
                if (tp.b1 - tp.b2 < MARGIN2) {
                    g_flag2[tt] = 1;
                    g_key[tt] = 0xFFFFFFFFFFFFFFFFULL;
                    int slot = atomicAdd(&g_nflag2, 1);
                    g_list2[slot] = tt;
                }
            }
        }
    }
}

// ---------------------------------------------------------------------------
// STAGE 3: exact fp32 re-argmax for stage-2 survivors, chip-parallel slices.
__global__ __launch_bounds__(256)
void k_refine(const float* __restrict__ z, const float* __restrict__ emb) {
    __shared__ float sx[C_DIM];
    __shared__ u64 rk[8];
    const int tid = threadIdx.x;
    const int lane = tid & 31;
    const int wid = tid >> 5;
    const int nf = g_nflag2;
    if (nf == 0) return;

    for (int wk = blockIdx.x; wk < nf * 64; wk += gridDim.x) {
        const int it = wk >> 6;
        const int slice = wk & 63;
        const int t = g_list2[it];
        __syncthreads();
        if (tid < C_DIM) {
            const float* zp = z + (size_t)(t >> 10) * (C_DIM * HW) + (t & 1023);
            sx[tid] = zp[tid * HW];
        }
        __syncthreads();

        u64 key = 0xFFFFFFFFFFFFFFFFULL;
        if (tid < 128) {
            int k = slice * 128 + tid;
            const float4* e4 = (const float4*)(emb + (size_t)k * C_DIM);
            float s = 0.0f;
            #pragma unroll
            for (int j = 0; j < 16; j++) {
                float4 e = e4[j];
                s += sx[4 * j] * e.x + sx[4 * j + 1] * e.y
                   + sx[4 * j + 2] * e.z + sx[4 * j + 3] * e.w;
            }
            s -= g_hn[k];
            key = ((u64)(~fmono(s)) << 32) | (u32)k;
        }
        #pragma unroll
        for (int o = 16; o > 0; o >>= 1) {
            u64 ok = __shfl_xor_sync(0xffffffffu, key, o);
            if (ok < key) key = ok;
        }
        if (lane == 0) rk[wid] = key;
        __syncthreads();
        if (tid == 0) {
            u64 kmin = rk[0];
            #pragma unroll
            for (int w2 = 1; w2 < 8; w2++) if (rk[w2] < kmin) kmin = rk[w2];
            atomicMin(&g_key[t], kmin);
        }
    }
}

// ---------------------------------------------------------------------------
// epilogue: indices, z_q, z_q_st, counts, dw  (4 threads per token)
__global__ __launch_bounds__(256)
void k_epi(const float* __restrict__ z, const float* __restrict__ emb,
           float* __restrict__ out) {
    const int gid = blockIdx.x * blockDim.x + threadIdx.x;
    const int t = gid >> 2;
    const int part = gid & 3;
    if (t >= N_TOK) return;
    const int b = t >> 10;
    const int hw = t & 1023;
    const float* zp = z + (size_t)b * (C_DIM * HW) + hw;

    int bi = g_flag2[t] ? (int)(u32)(g_key[t] & 0xFFFFFFFFULL) : g_idx[t];
    if (part == 0) {
        out[O_IDX + t] = (float)bi;
        atomicAdd(&g_counts[bi], 1.0f);
    }

    const float4* er = (const float4*)(emb + (size_t)bi * C_DIM) + part * 4;
    float* dwp = g_dw + (size_t)bi * C_DIM;
    float* zq   = out + O_ZQ   + (size_t)b * (C_DIM * HW) + hw;
    float* zqst = out + O_ZQST + (size_t)b * (C_DIM * HW) + hw;

    #pragma unroll
    for (int j = 0; j < 4; j++) {
        float4 q = er[j];
        int c = part * 16 + 4 * j;
        float x0 = zp[(c + 0) * HW];
        float x1 = zp[(c + 1) * HW];
        float x2 = zp[(c + 2) * HW];
        float x3 = zp[(c + 3) * HW];
        zq[(c + 0) * HW] = q.x;
        zq[(c + 1) * HW] = q.y;
        zq[(c + 2) * HW] = q.z;
        zq[(c + 3) * HW] = q.w;
        zqst[(c + 0) * HW] = x0 + (q.x - x0);
        zqst[(c + 1) * HW] = x1 + (q.y - x1);
        zqst[(c + 2) * HW] = x2 + (q.z - x2);
        zqst[(c + 3) * HW] = x3 + (q.w - x3);
        atomicAdd(dwp + c + 0, x0);
        atomicAdd(dwp + c + 1, x1);
        atomicAdd(dwp + c + 2, x2);
        atomicAdd(dwp + c + 3, x3);
    }
}

// ---------------------------------------------------------------------------
__global__ __launch_bounds__(256)
void k_cs(const float* __restrict__ cs, float* __restrict__ out) {
    const float OMD = 0.01f;
    int i = blockIdx.x * 256 + threadIdx.x;
    float v = 0.99f * cs[i] + OMD * g_counts[i];
    out[O_CS + i] = v;
    #pragma unroll
    for (int o = 16; o > 0; o >>= 1) v += __shfl_xor_sync(0xffffffffu, v, o);
    __shared__ float red[8];
    if ((threadIdx.x & 31) == 0) red[threadIdx.x >> 5] = v;
    __syncthreads();
    if (threadIdx.x == 0) {
        float s = red[0];
        #pragma unroll
        for (int w2 = 1; w2 < 8; w2++) s += red[w2];
        atomicAdd(&g_n, s);
    }
}

__global__ void k_emb(const float* __restrict__ cs, const float* __restrict__ avg,
                      float* __restrict__ out) {
    const float OMD = 0.01f;
    const float EPSF = 1e-5f;
    int i = blockIdx.x * blockDim.x + threadIdx.x;
    if (i >= K_CODES * C_DIM) return;
    int k = i >> 6;
    float ncs = 0.99f * cs[k] + OMD * g_counts[k];
    float navg = 0.99f * avg[i] + OMD * g_dw[i];
    float n = g_n;
    float denom = (ncs + EPSF) / (n + (float)K_CODES * EPSF) * n;
    out[O_EMB + i] = navg / denom;
    out[O_AVG + i] = navg;
}

// ---------------------------------------------------------------------------
extern "C" void kernel_launch(void* const* d_in, const int* in_sizes, int n_in,
                              void* d_out, int out_size) {
    const float* z   = (const float*)d_in[0];
    const float* emb = (const float*)d_in[1];
    const float* cs  = (const float*)d_in[2];
    const float* avg = (const float*)d_in[3];
    float* out = (float*)d_out;

    cudaFuncSetAttribute(k_dist1, cudaFuncAttributeMaxDynamicSharedMemorySize, SMEM1_TOTAL);
    cudaFuncSetAttribute(k_dist2, cudaFuncAttributeMaxDynamicSharedMemorySize, SMEM2_TOTAL);

    k_init<<<(K_CODES * C_DIM + 255) / 256, 256>>>();
    k_splitE<<<(K_CODES * 32 + 255) / 256, 256>>>(emb);
    k_dist1<<<N_TOK / MTILE, TPB, SMEM1_TOTAL>>>(z);
    k_dist2<<<N_TOK / MTILE, TPB, SMEM2_TOTAL>>>(z);
    k_refine<<<128, 256>>>(z, emb);
    k_epi<<<(4 * N_TOK + 255) / 256, 256>>>(z, emb, out);
    k_cs<<<K_CODES / 256, 256>>>(cs, out);
    k_emb<<<(K_CODES * C_DIM + 255) / 256, 256>>>(cs, avg, out);
}

// round 10
// speedup vs baseline: 1.8035x; 1.8035x over previous
#include <cuda_runtime.h>
#include <cuda_fp16.h>
#include <cstdint>

#define K_CODES 8192
#define C_DIM   64
#define N_TOK   16384
#define HW      1024
#define TPB     256
#define MTILE   128                  // tokens per CTA
#define NTILE   64                   // codes per tile
#define NTILES  (K_CODES / NTILE)    // 128
#define NSLICE  8                    // K slices in stage 2
#define TPSLICE (NTILES / NSLICE)    // 16 tiles per slice
#define MARGIN1 0.28f                // deterministic 1-term fp16 bound
#define MARGIN2 1e-4f                // proven in R5-R8

// output layout (float32, concatenated in reference return order)
#define O_ZQST 0
#define O_IDX  1048576
#define O_ZQ   1064960
#define O_EMB  2113536
#define O_CS   2637824
#define O_AVG  2646016

// smem layout for k_dist1 (1 comp)
#define SM1_A   0
#define SM1_B   16384
#define SM1_HN  32768
#define SMEM1_TOTAL (32768 + 512 + 128)

// smem layout for k_dist2 (2 comps)
#define SM_A    0
#define SM_B    32768
#define SM_HN   65536
#define SMEM2_TOTAL (65536 + 512 + 128)

typedef unsigned long long u64;
typedef unsigned int u32;

static __device__ __half g_Eh[K_CODES * C_DIM];
static __device__ __half g_Er[K_CODES * C_DIM];
static __device__ float g_hn[K_CODES];
static __device__ int   g_idx[N_TOK];
static __device__ int   g_flag2[N_TOK];
static __device__ u64   g_key[N_TOK];
static __device__ int   g_list[N_TOK];
static __device__ int   g_list2[N_TOK];
static __device__ int   g_nflag;
static __device__ int   g_nflag2;
static __device__ float g_s2b1[N_TOK * NSLICE];
static __device__ float g_s2b2[N_TOK * NSLICE];
static __device__ int   g_s2i1[N_TOK * NSLICE];
static __device__ float g_counts[K_CODES];
static __device__ float g_dw[K_CODES * C_DIM];
static __device__ float g_n;

// ---------------------------------------------------------------- helpers
__device__ __forceinline__ uint32_t smem_u32(const void* p) {
    uint32_t a;
    asm("{ .reg .u64 t; cvta.to.shared.u64 t, %1; cvt.u32.u64 %0, t; }"
        : "=r"(a) : "l"(p));
    return a;
}
__device__ __forceinline__ void cp_async16(uint32_t saddr, const void* gmem) {
    asm volatile("cp.async.cg.shared.global [%0], [%1], 16;\n" :: "r"(saddr), "l"(gmem));
}
#define CP_COMMIT() asm volatile("cp.async.commit_group;\n" ::: "memory")
#define CP_WAIT(n)  asm volatile("cp.async.wait_group %0;\n" :: "n"(n) : "memory")

__device__ __forceinline__ uint32_t sw128(uint32_t off) {
    return off ^ ((off >> 3) & 0x70);
}
__device__ __forceinline__ void ldsm4(u32& r0, u32& r1, u32& r2, u32& r3, uint32_t addr) {
    asm volatile("ldmatrix.sync.aligned.m8n8.x4.shared.b16 {%0,%1,%2,%3}, [%4];"
                 : "=r"(r0), "=r"(r1), "=r"(r2), "=r"(r3) : "r"(addr));
}
__device__ __forceinline__ void mma16816(float& d0, float& d1, float& d2, float& d3,
                                         u32 a0, u32 a1, u32 a2, u32 a3,
                                         u32 b0, u32 b1) {
    asm volatile("mma.sync.aligned.m16n8k16.row.col.f32.f16.f16.f32 "
                 "{%0,%1,%2,%3}, {%4,%5,%6,%7}, {%8,%9}, {%0,%1,%2,%3};"
                 : "+f"(d0), "+f"(d1), "+f"(d2), "+f"(d3)
                 : "r"(a0), "r"(a1), "r"(a2), "r"(a3), "r"(b0), "r"(b1));
}
__device__ __forceinline__ u32 fmono(float s) {
    u32 u = __float_as_uint(s);
    return (s < 0.0f) ? ~u : (u | 0x80000000u);
}

struct Top2 { float b1, b2; int i1; };
__device__ __forceinline__ void t2_push(Top2& t, float s, int idx) {
    if (s > t.b1) { t.b2 = t.b1; t.b1 = s; t.i1 = idx; }
    else if (s > t.b2) t.b2 = s;
}
__device__ __forceinline__ void t2_merge_shfl(Top2& t, int o) {
    float ob1 = __shfl_xor_sync(0xffffffffu, t.b1, o);
    float ob2 = __shfl_xor_sync(0xffffffffu, t.b2, o);
    int   oi1 = __shfl_xor_sync(0xffffffffu, t.i1, o);
    if (ob1 > t.b1 || (ob1 == t.b1 && oi1 < t.i1)) {
        t.b2 = fmaxf(t.b1, ob2); t.b1 = ob1; t.i1 = oi1;
    } else {
        t.b2 = fmaxf(t.b2, ob1);
    }
}

// ---------------------------------------------------------------------------
__global__ void k_init() {
    int i = blockIdx.x * blockDim.x + threadIdx.x;
    if (i < K_CODES) g_counts[i] = 0.0f;
    if (i < K_CODES * C_DIM) g_dw[i] = 0.0f;
    if (i < N_TOK) g_flag2[i] = 0;
    if (i == 0) { g_nflag = 0; g_nflag2 = 0; g_n = 0.0f; }
}

__global__ void k_splitE(const float* __restrict__ emb) {
    int w = (blockIdx.x * blockDim.x + threadIdx.x) >> 5;
    int lane = threadIdx.x & 31;
    if (w >= K_CODES) return;
    float s = 0.0f;
    #pragma unroll
    for (int half = 0; half < 2; half++) {
        int c = lane + half * 32;
        float x = emb[w * C_DIM + c];
        s += x * x;
        __half h = __float2half_rn(x);
        float r = x - __half2float(h);
        g_Eh[w * C_DIM + c] = h;
        g_Er[w * C_DIM + c] = __float2half_rn(r);
    }
    #pragma unroll
    for (int o = 16; o > 0; o >>= 1) s += __shfl_xor_sync(0xffffffffu, s, o);
    if (lane == 0) g_hn[w] = 0.5f * s;
}

// ---------------------------------------------------------------------------
// STAGE 1: coarse scores, hh term only; flags gap < MARGIN1 (worst-case bound).
__global__ void __launch_bounds__(TPB, 1) k_dist1(const float* __restrict__ z) {
    extern __shared__ char smem[];
    const uint32_t sb = smem_u32(smem);
    const int tid = threadIdx.x;
    const int lane = tid & 31;
    const int w = tid >> 5;

    {
        int r = tid & 127;
        int half = tid >> 7;
        int t = blockIdx.x * MTILE + r;
        const float* zp = z + (size_t)(t >> 10) * (C_DIM * HW) + (t & 1023);
        #pragma unroll
        for (int j = 0; j < 32; j++) {
            int c = half * 32 + j;
            uint32_t off = sw128((uint32_t)(r * 128 + c * 2));
            *(__half*)(smem + SM1_A + off) = __float2half_rn(zp[c * HW]);
        }
    }
    __syncthreads();

    u32 afr[4][4];
    {
        int arow = w * 16 + (lane & 7) + ((lane >> 3) & 1) * 8;
        int akb  = (lane >> 4) * 16;
        #pragma unroll
        for (int q = 0; q < 4; q++) {
            uint32_t addr = sb + SM1_A + sw128((uint32_t)(arow * 128 + q * 32 + akb));
            ldsm4(afr[q][0], afr[q][1], afr[q][2], afr[q][3], addr);
        }
    }

    auto load_tile = [&](int tile, int bufi) {
        const char* src = (const char*)g_Eh + (size_t)tile * (NTILE * C_DIM * 2);
        uint32_t dst = sb + SM1_B + (uint32_t)bufi * 8192u;
        #pragma unroll
        for (int u = 0; u < 2; u++) {
            uint32_t off = (uint32_t)(u * TPB + tid) * 16u;
            cp_async16(dst + sw128(off), src + off);
        }
        if (tid < 16)
            cp_async16(sb + SM1_HN + bufi * 256 + tid * 16,
                       (const char*)(g_hn + tile * NTILE) + tid * 16);
    };

    const int brow = (lane & 7) + ((lane >> 4) & 1) * 8;
    const int bkb  = ((lane >> 3) & 1) * 16;

    Top2 t0 = {-3.4e38f, -3.4e38f, 0};
    Top2 t1 = {-3.4e38f, -3.4e38f, 0};

    load_tile(0, 0); CP_COMMIT();
    load_tile(1, 1); CP_COMMIT();

    for (int ci = 0; ci < NTILES; ci++) {
        const int buf = ci & 1;
        if (ci + 1 < NTILES) { CP_WAIT(1); } else { CP_WAIT(0); }
        __syncthreads();

        float acc[8][4];
        #pragma unroll
        for (int g = 0; g < 8; g++)
            #pragma unroll
            for (int v = 0; v < 4; v++) acc[g][v] = 0.0f;

        uint32_t bbase = sb + SM1_B + (uint32_t)buf * 8192u;
        #pragma unroll
        for (int q = 0; q < 4; q++) {
            u32 bfr[8][2];
            #pragma unroll
            for (int g2 = 0; g2 < 4; g2++) {
                uint32_t addr = bbase +
                    sw128((uint32_t)((g2 * 16 + brow) * 128 + q * 32 + bkb));
                ldsm4(bfr[2 * g2][0], bfr[2 * g2][1],
                      bfr[2 * g2 + 1][0], bfr[2 * g2 + 1][1], addr);
            }
            #pragma unroll
            for (int g = 0; g < 8; g++)
                mma16816(acc[g][0], acc[g][1], acc[g][2], acc[g][3],
                         afr[q][0], afr[q][1], afr[q][2], afr[q][3],
                         bfr[g][0], bfr[g][1]);
        }

        const float* hnp = (const float*)(smem + SM1_HN + buf * 256);
        const int colbase = ci * NTILE + 2 * (lane & 3);
        #pragma unroll
        for (int g = 0; g < 8; g++) {
            int lc = g * 8 + 2 * (lane & 3);
            float h0 = hnp[lc], h1 = hnp[lc + 1];
            int c0 = colbase + g * 8, c1 = c0 + 1;
            t2_push(t0, acc[g][0] - h0, c0);
            t2_push(t0, acc[g][1] - h1, c1);
            t2_push(t1, acc[g][2] - h0, c0);
            t2_push(t1, acc[g][3] - h1, c1);
        }

        __syncthreads();
        if (ci + 2 < NTILES) { load_tile(ci + 2, buf); CP_COMMIT(); }
    }

    #pragma unroll
    for (int o = 1; o <= 2; o <<= 1) { t2_merge_shfl(t0, o); t2_merge_shfl(t1, o); }

    if ((lane & 3) == 0) {
        int r = w * 16 + (lane >> 2);
        int tt = blockIdx.x * MTILE + r;
        g_idx[tt] = t0.i1;
        if (t0.b1 - t0.b2 < MARGIN1) {
            int slot = atomicAdd(&g_nflag, 1);
            g_list[slot] = tt;
        }
        g_idx[tt + 8] = t1.i1;
        if (t1.b1 - t1.b2 < MARGIN1) {
            int slot = atomicAdd(&g_nflag, 1);
            g_list[slot] = tt + 8;
        }
    }
}

// ---------------------------------------------------------------------------
// STAGE 2: 3-term scores for flagged tokens over ONE K-slice (16 tiles).
// grid = (128 token-tiles, NSLICE); inactive blocks exit. Per-slice top-2
// written to g_s2*; merged per token by k_resolve.
__global__ void __launch_bounds__(TPB, 1) k_dist2(const float* __restrict__ z) {
    const int nf = g_nflag;
    if ((int)blockIdx.x * MTILE >= nf) return;

    extern __shared__ char smem[];
    const uint32_t sb = smem_u32(smem);
    const int tid = threadIdx.x;
    const int lane = tid & 31;
    const int w = tid >> 5;
    const int slice = blockIdx.y;
    const int ci0 = slice * TPSLICE;
    const int ci1 = ci0 + TPSLICE;

    // gather flagged tokens, 2-way fp16 split
    {
        int r = tid & 127;
        int half = tid >> 7;
        int li = blockIdx.x * MTILE + r;
        int t = g_list[(li < nf) ? li : 0];
        const float* zp = z + (size_t)(t >> 10) * (C_DIM * HW) + (t & 1023);
        #pragma unroll
        for (int j = 0; j < 32; j++) {
            int c = half * 32 + j;
            float x = zp[c * HW];
            __half h = __float2half_rn(x);
            float rr = x - __half2float(h);
            uint32_t off = sw128((uint32_t)(r * 128 + c * 2));
            *(__half*)(smem + SM_A + off) = h;
            *(__half*)(smem + SM_A + 16384 + off) = __float2half_rn(rr);
        }
    }
    __syncthreads();

    u32 afr[2][4][4];
    {
        int arow = w * 16 + (lane & 7) + ((lane >> 3) & 1) * 8;
        int akb  = (lane >> 4) * 16;
        #pragma unroll
        for (int c = 0; c < 2; c++)
            #pragma unroll
            for (int q = 0; q < 4; q++) {
                uint32_t addr = sb + SM_A + c * 16384 +
                                sw128((uint32_t)(arow * 128 + q * 32 + akb));
                ldsm4(afr[c][q][0], afr[c][q][1], afr[c][q][2], afr[c][q][3], addr);
            }
    }

    auto load_tile = [&](int tile, int bufi) {
        const char* srcs[2] = {(const char*)g_Eh, (const char*)g_Er};
        #pragma unroll
        for (int c = 0; c < 2; c++) {
            const char* src = srcs[c] + (size_t)tile * (NTILE * C_DIM * 2);
            uint32_t dst = sb + SM_B + (uint32_t)(bufi * 2 + c) * 8192u;
            #pragma unroll
            for (int u = 0; u < 2; u++) {
                uint32_t off = (uint32_t)(u * TPB + tid) * 16u;
                cp_async16(dst + sw128(off), src + off);
            }
        }
        if (tid < 16)
            cp_async16(sb + SM_HN + bufi * 256 + tid * 16,
                       (const char*)(g_hn + tile * NTILE) + tid * 16);
    };

    const int brow = (lane & 7) + ((lane >> 4) & 1) * 8;
    const int bkb  = ((lane >> 3) & 1) * 16;

    Top2 t0 = {-3.4e38f, -3.4e38f, 0};
    Top2 t1 = {-3.4e38f, -3.4e38f, 0};

    load_tile(ci0, 0); CP_COMMIT();
    load_tile(ci0 + 1, 1); CP_COMMIT();

    for (int ci = ci0; ci < ci1; ci++) {
        const int buf = ci & 1;
        if (ci + 1 < ci1) { CP_WAIT(1); } else { CP_WAIT(0); }
        __syncthreads();

        float acc[8][4];
        #pragma unroll
        for (int g = 0; g < 8; g++)
            #pragma unroll
            for (int v = 0; v < 4; v++) acc[g][v] = 0.0f;

        #pragma unroll
        for (int q = 0; q < 4; q++) {
            u32 bfr[8][2];
            uint32_t b0base = sb + SM_B + (uint32_t)(buf * 2) * 8192u;
            #pragma unroll
            for (int g2 = 0; g2 < 4; g2++) {
                uint32_t addr = b0base +
                    sw128((uint32_t)((g2 * 16 + brow) * 128 + q * 32 + bkb));
                ldsm4(bfr[2 * g2][0], bfr[2 * g2][1],
                      bfr[2 * g2 + 1][0], bfr[2 * g2 + 1][1], addr);
            }
            #pragma unroll
            for (int g = 0; g < 8; g++) {
                mma16816(acc[g][0], acc[g][1], acc[g][2], acc[g][3],
                         afr[0][q][0], afr[0][q][1], afr[0][q][2], afr[0][q][3],
                         bfr[g][0], bfr[g][1]);
                mma16816(acc[g][0], acc[g][1], acc[g][2], acc[g][3],
                         afr[1][q][0], afr[1][q][1], afr[1][q][2], afr[1][q][3],
                         bfr[g][0], bfr[g][1]);
            }
            uint32_t b1base = sb + SM_B + (uint32_t)(buf * 2 + 1) * 8192u;
            #pragma unroll
            for (int g2 = 0; g2 < 4; g2++) {
                uint32_t addr = b1base +
                    sw128((uint32_t)((g2 * 16 + brow) * 128 + q * 32 + bkb));
                ldsm4(bfr[2 * g2][0], bfr[2 * g2][1],
                      bfr[2 * g2 + 1][0], bfr[2 * g2 + 1][1], addr);
            }
            #pragma unroll
            for (int g = 0; g < 8; g++)
                mma16816(acc[g][0], acc[g][1], acc[g][2], acc[g][3],
                         afr[0][q][0], afr[0][q][1], afr[0][q][2], afr[0][q][3],
                         bfr[g][0], bfr[g][1]);
        }

        const float* hnp = (const float*)(smem + SM_HN + buf * 256);
        const int colbase = ci * NTILE + 2 * (lane & 3);
        #pragma unroll
        for (int g = 0; g < 8; g++) {
            int lc = g * 8 + 2 * (lane & 3);
            float h0 = hnp[lc], h1 = hnp[lc + 1];
            int c0 = colbase + g * 8, c1 = c0 + 1;
            t2_push(t0, acc[g][0] - h0, c0);
            t2_push(t0, acc[g][1] - h1, c1);
            t2_push(t1, acc[g][2] - h0, c0);
            t2_push(t1, acc[g][3] - h1, c1);
        }

        __syncthreads();
        if (ci + 2 < ci1) { load_tile(ci + 2, buf); CP_COMMIT(); }
    }

    #pragma unroll
    for (int o = 1; o <= 2; o <<= 1) { t2_merge_shfl(t0, o); t2_merge_shfl(t1, o); }

    if ((lane & 3) == 0) {
        int r = w * 16 + (lane >> 2);
        #pragma unroll
        for (int pair = 0; pair < 2; pair++) {
            Top2& tp = pair ? t1 : t0;
            int li = blockIdx.x * MTILE + r + pair * 8;
            if (li < nf) {
                g_s2b1[li * NSLICE + slice] = tp.b1;
                g_s2b2[li * NSLICE + slice] = tp.b2;
                g_s2i1[li * NSLICE + slice] = tp.i1;
            }
        }
    }
}

// ---------------------------------------------------------------------------
// merge per-slice top-2 -> global top-2 per flagged token; enqueue MARGIN2
// failures for exact refine. Ascending slice order keeps first-occurrence ties.
__global__ __launch_bounds__(256)
void k_resolve() {
    int li = blockIdx.x * 256 + threadIdx.x;
    if (li >= g_nflag) return;
    int t = g_list[li];
    float B1 = -3.4e38f, B2 = -3.4e38f;
    int I1 = 0;
    #pragma unroll
    for (int s = 0; s < NSLICE; s++) {
        float b1 = g_s2b1[li * NSLICE + s];
        float b2 = g_s2b2[li * NSLICE + s];
        int   i1 = g_s2i1[li * NSLICE + s];
        if (b1 > B1) { B2 = fmaxf(B1, b2); B1 = b1; I1 = i1; }
        else { B2 = fmaxf(B2, b1); }
    }
    g_idx[t] = I1;
    if (B1 - B2 < MARGIN2) {
        g_flag2[t] = 1;
        g_key[t] = 0xFFFFFFFFFFFFFFFFULL;
        int slot = atomicAdd(&g_nflag2, 1);
        g_list2[slot] = t;
    }
}

// ---------------------------------------------------------------------------
// exact fp32 re-argmax for stage-2 survivors, chip-parallel K slices.
__global__ __launch_bounds__(256)
void k_refine(const float* __restrict__ z, const float* __restrict__ emb) {
    __shared__ float sx[C_DIM];
    __shared__ u64 rk[8];
    const int tid = threadIdx.x;
    const int lane = tid & 31;
    const int wid = tid >> 5;
    const int nf = g_nflag2;
    if (nf == 0) return;

    for (int wk = blockIdx.x; wk < nf * 64; wk += gridDim.x) {
        const int it = wk >> 6;
        const int slice = wk & 63;
        const int t = g_list2[it];
        __syncthreads();
        if (tid < C_DIM) {
            const float* zp = z + (size_t)(t >> 10) * (C_DIM * HW) + (t & 1023);
            sx[tid] = zp[tid * HW];
        }
        __syncthreads();

        u64 key = 0xFFFFFFFFFFFFFFFFULL;
        if (tid < 128) {
            int k = slice * 128 + tid;
            const float4* e4 = (const float4*)(emb + (size_t)k * C_DIM);
            float s = 0.0f;
            #pragma unroll
            for (int j = 0; j < 16; j++) {
                float4 e = e4[j];
                s += sx[4 * j] * e.x + sx[4 * j + 1] * e.y
                   + sx[4 * j + 2] * e.z + sx[4 * j + 3] * e.w;
            }
            s -= g_hn[k];
            key = ((u64)(~fmono(s)) << 32) | (u32)k;
        }
        #pragma unroll
        for (int o = 16; o > 0; o >>= 1) {
            u64 ok = __shfl_xor_sync(0xffffffffu, key, o);
            if (ok < key) key = ok;
        }
        if (lane == 0) rk[wid] = key;
        __syncthreads();
        if (tid == 0) {
            u64 kmin = rk[0];
            #pragma unroll
            for (int w2 = 1; w2 < 8; w2++) if (rk[w2] < kmin) kmin = rk[w2];
            atomicMin(&g_key[t], kmin);
        }
    }
}

// ---------------------------------------------------------------------------
__global__ __launch_bounds__(256)
void k_epi(const float* __restrict__ z, const float* __restrict__ emb,
           float* __restrict__ out) {
    const int gid = blockIdx.x * blockDim.x + threadIdx.x;
    const int t = gid >> 2;
    const int part = gid & 3;
    if (t >= N_TOK) return;
    const int b = t >> 10;
    const int hw = t & 1023;
    const float* zp = z + (size_t)b * (C_DIM * HW) + hw;

    int bi = g_flag2[t] ? (int)(u32)(g_key[t] & 0xFFFFFFFFULL) : g_idx[t];
    if (part == 0) {
        out[O_IDX + t] = (float)bi;
        atomicAdd(&g_counts[bi], 1.0f);
    }

    const float4* er = (const float4*)(emb + (size_t)bi * C_DIM) + part * 4;
    float* dwp = g_dw + (size_t)bi * C_DIM;
    float* zq   = out + O_ZQ   + (size_t)b * (C_DIM * HW) + hw;
    float* zqst = out + O_ZQST + (size_t)b * (C_DIM * HW) + hw;

    #pragma unroll
    for (int j = 0; j < 4; j++) {
        float4 q = er[j];
        int c = part * 16 + 4 * j;
        float x0 = zp[(c + 0) * HW];
        float x1 = zp[(c + 1) * HW];
        float x2 = zp[(c + 2) * HW];
        float x3 = zp[(c + 3) * HW];
        zq[(c + 0) * HW] = q.x;
        zq[(c + 1) * HW] = q.y;
        zq[(c + 2) * HW] = q.z;
        zq[(c + 3) * HW] = q.w;
        zqst[(c + 0) * HW] = x0 + (q.x - x0);
        zqst[(c + 1) * HW] = x1 + (q.y - x1);
        zqst[(c + 2) * HW] = x2 + (q.z - x2);
        zqst[(c + 3) * HW] = x3 + (q.w - x3);
        atomicAdd(dwp + c + 0, x0);
        atomicAdd(dwp + c + 1, x1);
        atomicAdd(dwp + c + 2, x2);
        atomicAdd(dwp + c + 3, x3);
    }
}

// ---------------------------------------------------------------------------
__global__ __launch_bounds__(256)
void k_cs(const float* __restrict__ cs, float* __restrict__ out) {
    const float OMD = 0.01f;
    int i = blockIdx.x * 256 + threadIdx.x;
    float v = 0.99f * cs[i] + OMD * g_counts[i];
    out[O_CS + i] = v;
    #pragma unroll
    for (int o = 16; o > 0; o >>= 1) v += __shfl_xor_sync(0xffffffffu, v, o);
    __shared__ float red[8];
    if ((threadIdx.x & 31) == 0) red[threadIdx.x >> 5] = v;
    __syncthreads();
    if (threadIdx.x == 0) {
        float s = red[0];
        #pragma unroll
        for (int w2 = 1; w2 < 8; w2++) s += red[w2];
        atomicAdd(&g_n, s);
    }
}

__global__ void k_emb(const float* __restrict__ cs, const float* __restrict__ avg,
                      float* __restrict__ out) {
    const float OMD = 0.01f;
    const float EPSF = 1e-5f;
    int i = blockIdx.x * blockDim.x + threadIdx.x;
    if (i >= K_CODES * C_DIM) return;
    int k = i >> 6;
    float ncs = 0.99f * cs[k] + OMD * g_counts[k];
    float navg = 0.99f * avg[i] + OMD * g_dw[i];
    float n = g_n;
    float denom = (ncs + EPSF) / (n + (float)K_CODES * EPSF) * n;
    out[O_EMB + i] = navg / denom;
    out[O_AVG + i] = navg;
}

// ---------------------------------------------------------------------------
extern "C" void kernel_launch(void* const* d_in, const int* in_sizes, int n_in,
                              void* d_out, int out_size) {
    const float* z   = (const float*)d_in[0];
    const float* emb = (const float*)d_in[1];
    const float* cs  = (const float*)d_in[2];
    const float* avg = (const float*)d_in[3];
    float* out = (float*)d_out;

    cudaFuncSetAttribute(k_dist1, cudaFuncAttributeMaxDynamicSharedMemorySize, SMEM1_TOTAL);
    cudaFuncSetAttribute(k_dist2, cudaFuncAttributeMaxDynamicSharedMemorySize, SMEM2_TOTAL);

    k_init<<<(K_CODES * C_DIM + 255) / 256, 256>>>();
    k_splitE<<<(K_CODES * 32 + 255) / 256, 256>>>(emb);
    k_dist1<<<N_TOK / MTILE, TPB, SMEM1_TOTAL>>>(z);
    k_dist2<<<dim3(N_TOK / MTILE, NSLICE), TPB, SMEM2_TOTAL>>>(z);
    k_resolve<<<N_TOK / 256, 256>>>();
    k_refine<<<128, 256>>>(z, emb);
    k_epi<<<(4 * N_TOK + 255) / 256, 256>>>(z, emb, out);
    k_cs<<<K_CODES / 256, 256>>>(cs, out);
    k_emb<<<(K_CODES * C_DIM + 255) / 256, 256>>>(cs, avg, out);
}

// round 11
// speedup vs baseline: 3.0316x; 1.6809x over previous
#include <cuda_runtime.h>
#include <cuda_fp16.h>
#include <cstdint>

#define K_CODES 8192
#define C_DIM   64
#define N_TOK   16384
#define HW      1024
#define TPB     256
#define MTILE   128
#define NTILE   64
#define NTILES  (K_CODES / NTILE)    // 128
#define NSLICE  8
#define TPSLICE (NTILES / NSLICE)    // 16
#define MARGIN1 0.28f                // deterministic 1-term fp16 bound
#define MARGIN2 1e-4f                // proven R5-R8

#define O_ZQST 0
#define O_IDX  1048576
#define O_ZQ   1064960
#define O_EMB  2113536
#define O_CS   2637824
#define O_AVG  2646016

#define SM1_A   0
#define SM1_B   16384
#define SM1_HN  32768
#define SMEM1_TOTAL (32768 + 512 + 128)

#define SM_A    0
#define SM_B    32768
#define SM_HN   65536
#define SMEM2_TOTAL (65536 + 512 + 128)

typedef unsigned long long u64;
typedef unsigned int u32;

static __device__ __half g_Eh[K_CODES * C_DIM];
static __device__ __half g_Er[K_CODES * C_DIM];
static __device__ __half g_Ph[N_TOK * C_DIM];   // packed flagged-token h
static __device__ __half g_Pr[N_TOK * C_DIM];   // packed flagged-token r
static __device__ float g_hn[K_CODES];
static __device__ int   g_idx[N_TOK];
static __device__ int   g_flag2[N_TOK];
static __device__ u64   g_key[N_TOK];
static __device__ int   g_list[N_TOK];
static __device__ int   g_list2[N_TOK];
static __device__ int   g_nflag;
static __device__ int   g_nflag2;
static __device__ float g_s2b1[N_TOK * NSLICE];
static __device__ float g_s2b2[N_TOK * NSLICE];
static __device__ int   g_s2i1[N_TOK * NSLICE];
static __device__ float g_counts[K_CODES];
static __device__ float g_dw[K_CODES * C_DIM];
static __device__ float g_n;

// ---------------------------------------------------------------- helpers
__device__ __forceinline__ uint32_t smem_u32(const void* p) {
    uint32_t a;
    asm("{ .reg .u64 t; cvta.to.shared.u64 t, %1; cvt.u32.u64 %0, t; }"
        : "=r"(a) : "l"(p));
    return a;
}
__device__ __forceinline__ void cp_async16(uint32_t saddr, const void* gmem) {
    asm volatile("cp.async.cg.shared.global [%0], [%1], 16;\n" :: "r"(saddr), "l"(gmem));
}
#define CP_COMMIT() asm volatile("cp.async.commit_group;\n" ::: "memory")
#define CP_WAIT(n)  asm volatile("cp.async.wait_group %0;\n" :: "n"(n) : "memory")

__device__ __forceinline__ uint32_t sw128(uint32_t off) {
    return off ^ ((off >> 3) & 0x70);
}
__device__ __forceinline__ void ldsm4(u32& r0, u32& r1, u32& r2, u32& r3, uint32_t addr) {
    asm volatile("ldmatrix.sync.aligned.m8n8.x4.shared.b16 {%0,%1,%2,%3}, [%4];"
                 : "=r"(r0), "=r"(r1), "=r"(r2), "=r"(r3) : "r"(addr));
}
__device__ __forceinline__ void mma16816(float& d0, float& d1, float& d2, float& d3,
                                         u32 a0, u32 a1, u32 a2, u32 a3,
                                         u32 b0, u32 b1) {
    asm volatile("mma.sync.aligned.m16n8k16.row.col.f32.f16.f16.f32 "
                 "{%0,%1,%2,%3}, {%4,%5,%6,%7}, {%8,%9}, {%0,%1,%2,%3};"
                 : "+f"(d0), "+f"(d1), "+f"(d2), "+f"(d3)
                 : "r"(a0), "r"(a1), "r"(a2), "r"(a3), "r"(b0), "r"(b1));
}
__device__ __forceinline__ u32 fmono(float s) {
    u32 u = __float_as_uint(s);
    return (s < 0.0f) ? ~u : (u | 0x80000000u);
}

// branchless top-2 merge; A preferred on tie (A carries smaller indices)
__device__ __forceinline__ void merge2(float& m1a, float& m2a, int& ia,
                                       float m1b, float m2b, int ib) {
    float mn = fminf(m1a, m1b);
    m2a = fmaxf(mn, fmaxf(m2a, m2b));
    ia = (m1a >= m1b) ? ia : ib;
    m1a = fmaxf(m1a, m1b);
}

// cross-lane top-2 merge with explicit index tie-break (disjoint index sets)
__device__ __forceinline__ void t2_merge_shfl(float& b1, float& b2, int& i1, int o) {
    float ob1 = __shfl_xor_sync(0xffffffffu, b1, o);
    float ob2 = __shfl_xor_sync(0xffffffffu, b2, o);
    int   oi1 = __shfl_xor_sync(0xffffffffu, i1, o);
    if (ob1 > b1 || (ob1 == b1 && oi1 < i1)) {
        b2 = fmaxf(b1, ob2); b1 = ob1; i1 = oi1;
    } else {
        b2 = fmaxf(b2, ob1);
    }
}

// per-tile tree top-2 over 16 scores (one token row), fold into running state
__device__ __forceinline__ void tile_top2(const float acc[8][4], int v0, int v1,
                                          const float* hnp, int lq, int colbase,
                                          float& b1, float& b2, int& i1) {
    float m1[8], m2[8]; int ii[8];
    #pragma unroll
    for (int g = 0; g < 8; g++) {
        int lc = g * 8 + lq;
        float sa = acc[g][v0] - hnp[lc];
        float sb = acc[g][v1] - hnp[lc + 1];
        m1[g] = fmaxf(sa, sb);
        m2[g] = fminf(sa, sb);
        ii[g] = (sa >= sb) ? (colbase + g * 8) : (colbase + g * 8 + 1);
    }
    #pragma unroll
    for (int st = 1; st < 8; st <<= 1)
        #pragma unroll
        for (int g = 0; g < 8; g += 2 * st)
            merge2(m1[g], m2[g], ii[g], m1[g + st], m2[g + st], ii[g + st]);
    merge2(b1, b2, i1, m1[0], m2[0], ii[0]);
}

// ---------------------------------------------------------------------------
__global__ void k_initA() {
    int i = blockIdx.x * blockDim.x + threadIdx.x;
    if (i < K_CODES * C_DIM) g_dw[i] = 0.0f;
}
__global__ void k_initB() {
    int i = blockIdx.x * blockDim.x + threadIdx.x;
    if (i < K_CODES) g_counts[i] = 0.0f;
    if (i < N_TOK) g_flag2[i] = 0;
    if (i == 0) { g_nflag = 0; g_nflag2 = 0; g_n = 0.0f; }
}

__global__ void k_splitE(const float* __restrict__ emb) {
    int w = (blockIdx.x * blockDim.x + threadIdx.x) >> 5;
    int lane = threadIdx.x & 31;
    if (w >= K_CODES) return;
    float s = 0.0f;
    #pragma unroll
    for (int half = 0; half < 2; half++) {
        int c = lane + half * 32;
        float x = emb[w * C_DIM + c];
        s += x * x;
        __half h = __float2half_rn(x);
        float r = x - __half2float(h);
        g_Eh[w * C_DIM + c] = h;
        g_Er[w * C_DIM + c] = __float2half_rn(r);
    }
    #pragma unroll
    for (int o = 16; o > 0; o >>= 1) s += __shfl_xor_sync(0xffffffffu, s, o);
    if (lane == 0) g_hn[w] = 0.5f * s;
}

// ---------------------------------------------------------------------------
// STAGE 1: coarse scores (hh only); flag gap < MARGIN1.  [captured launch #4]
__global__ void __launch_bounds__(TPB, 1) k_dist1(const float* __restrict__ z) {
    extern __shared__ char smem[];
    const uint32_t sb = smem_u32(smem);
    const int tid = threadIdx.x;
    const int lane = tid & 31;
    const int w = tid >> 5;

    {
        int r = tid & 127;
        int half = tid >> 7;
        int t = blockIdx.x * MTILE + r;
        const float* zp = z + (size_t)(t >> 10) * (C_DIM * HW) + (t & 1023);
        #pragma unroll
        for (int j = 0; j < 32; j++) {
            int c = half * 32 + j;
            uint32_t off = sw128((uint32_t)(r * 128 + c * 2));
            *(__half*)(smem + SM1_A + off) = __float2half_rn(zp[c * HW]);
        }
    }
    __syncthreads();

    u32 afr[4][4];
    {
        int arow = w * 16 + (lane & 7) + ((lane >> 3) & 1) * 8;
        int akb  = (lane >> 4) * 16;
        #pragma unroll
        for (int q = 0; q < 4; q++) {
            uint32_t addr = sb + SM1_A + sw128((uint32_t)(arow * 128 + q * 32 + akb));
            ldsm4(afr[q][0], afr[q][1], afr[q][2], afr[q][3], addr);
        }
    }

    auto load_tile = [&](int tile, int bufi) {
        const char* src = (const char*)g_Eh + (size_t)tile * (NTILE * C_DIM * 2);
        uint32_t dst = sb + SM1_B + (uint32_t)bufi * 8192u;
        #pragma unroll
        for (int u = 0; u < 2; u++) {
            uint32_t off = (uint32_t)(u * TPB + tid) * 16u;
            cp_async16(dst + sw128(off), src + off);
        }
        if (tid < 16)
            cp_async16(sb + SM1_HN + bufi * 256 + tid * 16,
                       (const char*)(g_hn + tile * NTILE) + tid * 16);
    };

    const int brow = (lane & 7) + ((lane >> 4) & 1) * 8;
    const int bkb  = ((lane >> 3) & 1) * 16;
    const int lq   = 2 * (lane & 3);

    float b1_0 = -3.4e38f, b2_0 = -3.4e38f;
    float b1_1 = -3.4e38f, b2_1 = -3.4e38f;
    int i1_0 = 0, i1_1 = 0;

    load_tile(0, 0); CP_COMMIT();
    load_tile(1, 1); CP_COMMIT();

    for (int ci = 0; ci < NTILES; ci++) {
        const int buf = ci & 1;
        if (ci + 1 < NTILES) { CP_WAIT(1); } else { CP_WAIT(0); }
        __syncthreads();

        float acc[8][4];
        #pragma unroll
        for (int g = 0; g < 8; g++)
            #pragma unroll
            for (int v = 0; v < 4; v++) acc[g][v] = 0.0f;

        uint32_t bbase = sb + SM1_B + (uint32_t)buf * 8192u;
        #pragma unroll
        for (int q = 0; q < 4; q++) {
            u32 bfr[8][2];
            #pragma unroll
            for (int g2 = 0; g2 < 4; g2++) {
                uint32_t addr = bbase +
                    sw128((uint32_t)((g2 * 16 + brow) * 128 + q * 32 + bkb));
                ldsm4(bfr[2 * g2][0], bfr[2 * g2][1],
                      bfr[2 * g2 + 1][0], bfr[2 * g2 + 1][1], addr);
            }
            #pragma unroll
            for (int g = 0; g < 8; g++)
                mma16816(acc[g][0], acc[g][1], acc[g][2], acc[g][3],
                         afr[q][0], afr[q][1], afr[q][2], afr[q][3],
                         bfr[g][0], bfr[g][1]);
        }

        const float* hnp = (const float*)(smem + SM1_HN + buf * 256);
        const int colbase = ci * NTILE + lq;
        tile_top2(acc, 0, 1, hnp, lq, colbase, b1_0, b2_0, i1_0);
        tile_top2(acc, 2, 3, hnp, lq, colbase, b1_1, b2_1, i1_1);

        __syncthreads();
        if (ci + 2 < NTILES) { load_tile(ci + 2, buf); CP_COMMIT(); }
    }

    #pragma unroll
    for (int o = 1; o <= 2; o <<= 1) {
        t2_merge_shfl(b1_0, b2_0, i1_0, o);
        t2_merge_shfl(b1_1, b2_1, i1_1, o);
    }

    if ((lane & 3) == 0) {
        int r = w * 16 + (lane >> 2);
        int tt = blockIdx.x * MTILE + r;
        g_idx[tt] = i1_0;
        if (b1_0 - b2_0 < MARGIN1) {
            int slot = atomicAdd(&g_nflag, 1);
            g_list[slot] = tt;
        }
        g_idx[tt + 8] = i1_1;
        if (b1_1 - b2_1 < MARGIN1) {
            int slot = atomicAdd(&g_nflag, 1);
            g_list[slot] = tt + 8;
        }
    }
}

// ---------------------------------------------------------------------------
// pack flagged tokens' fp16 split contiguously for stage 2
__global__ __launch_bounds__(256)
void k_pack(const float* __restrict__ z) {
    int nf = g_nflag;
    int total = nf * C_DIM;
    for (int i = blockIdx.x * 256 + threadIdx.x; i < total; i += gridDim.x * 256) {
        int li = i >> 6, c = i & 63;
        int t = g_list[li];
        float x = z[(size_t)(t >> 10) * (C_DIM * HW) + c * HW + (t & 1023)];
        __half h = __float2half_rn(x);
        g_Ph[i] = h;
        g_Pr[i] = __float2half_rn(x - __half2float(h));
    }
}

// ---------------------------------------------------------------------------
// STAGE 2: 3-term scores for flagged tokens over one K-slice (16 tiles).
__global__ void __launch_bounds__(TPB, 1) k_dist2() {
    const int nf = g_nflag;
    if ((int)blockIdx.x * MTILE >= nf) return;

    extern __shared__ char smem[];
    const uint32_t sb = smem_u32(smem);
    const int tid = threadIdx.x;
    const int lane = tid & 31;
    const int w = tid >> 5;
    const int slice = blockIdx.y;
    const int ci0 = slice * TPSLICE;
    const int ci1 = ci0 + TPSLICE;

    // coalesced load of packed A (h and r), 128B per token row
    {
        int r = tid & 127;
        int half = tid >> 7;
        int li = blockIdx.x * MTILE + r;
        size_t rowo = (size_t)((li < nf) ? li : 0) * C_DIM;
        const uint4* srch = (const uint4*)(g_Ph + rowo);
        const uint4* srcr = (const uint4*)(g_Pr + rowo);
        #pragma unroll
        for (int j = 0; j < 4; j++) {
            int chunk = half * 4 + j;
            uint32_t off = sw128((uint32_t)(r * 128 + chunk * 16));
            *(uint4*)(smem + SM_A + off) = srch[chunk];
            *(uint4*)(smem + SM_A + 16384 + off) = srcr[chunk];
        }
    }
    __syncthreads();

    u32 afr[2][4][4];
    {
        int arow = w * 16 + (lane & 7) + ((lane >> 3) & 1) * 8;
        int akb  = (lane >> 4) * 16;
        #pragma unroll
        for (int c = 0; c < 2; c++)
            #pragma unroll
            for (int q = 0; q < 4; q++) {
                uint32_t addr = sb + SM_A + c * 16384 +
                                sw128((uint32_t)(arow * 128 + q * 32 + akb));
                ldsm4(afr[c][q][0], afr[c][q][1], afr[c][q][2], afr[c][q][3], addr);
            }
    }

    auto load_tile = [&](int tile, int bufi) {
        const char* srcs[2] = {(const char*)g_Eh, (const char*)g_Er};
        #pragma unroll
        for (int c = 0; c < 2; c++) {
            const char* src = srcs[c] + (size_t)tile * (NTILE * C_DIM * 2);
            uint32_t dst = sb + SM_B + (uint32_t)(bufi * 2 + c) * 8192u;
            #pragma unroll
            for (int u = 0; u < 2; u++) {
                uint32_t off = (uint32_t)(u * TPB + tid) * 16u;
                cp_async16(dst + sw128(off), src + off);
            }
        }
        if (tid < 16)
            cp_async16(sb + SM_HN + bufi * 256 + tid * 16,
                       (const char*)(g_hn + tile * NTILE) + tid * 16);
    };

    const int brow = (lane & 7) + ((lane >> 4) & 1) * 8;
    const int bkb  = ((lane >> 3) & 1) * 16;
    const int lq   = 2 * (lane & 3);

    float b1_0 = -3.4e38f, b2_0 = -3.4e38f;
    float b1_1 = -3.4e38f, b2_1 = -3.4e38f;
    int i1_0 = 0, i1_1 = 0;

    load_tile(ci0, 0); CP_COMMIT();
    load_tile(ci0 + 1, 1); CP_COMMIT();

    for (int ci = ci0; ci < ci1; ci++) {
        const int buf = ci & 1;
        if (ci + 1 < ci1) { CP_WAIT(1); } else { CP_WAIT(0); }
        __syncthreads();

        float acc[8][4];
        #pragma unroll
        for (int g = 0; g < 8; g++)
            #pragma unroll
            for (int v = 0; v < 4; v++) acc[g][v] = 0.0f;

        #pragma unroll
        for (int q = 0; q < 4; q++) {
            u32 bfr[8][2];
            uint32_t b0base = sb + SM_B + (uint32_t)(buf * 2) * 8192u;
            #pragma unroll
            for (int g2 = 0; g2 < 4; g2++) {
                uint32_t addr = b0base +
                    sw128((uint32_t)((g2 * 16 + brow) * 128 + q * 32 + bkb));
                ldsm4(bfr[2 * g2][0], bfr[2 * g2][1],
                      bfr[2 * g2 + 1][0], bfr[2 * g2 + 1][1], addr);
            }
            #pragma unroll
            for (int g = 0; g < 8; g++) {
                mma16816(acc[g][0], acc[g][1], acc[g][2], acc[g][3],
                         afr[0][q][0], afr[0][q][1], afr[0][q][2], afr[0][q][3],
                         bfr[g][0], bfr[g][1]);
                mma16816(acc[g][0], acc[g][1], acc[g][2], acc[g][3],
                         afr[1][q][0], afr[1][q][1], afr[1][q][2], afr[1][q][3],
                         bfr[g][0], bfr[g][1]);
            }
            uint32_t b1base = sb + SM_B + (uint32_t)(buf * 2 + 1) * 8192u;
            #pragma unroll
            for (int g2 = 0; g2 < 4; g2++) {
                uint32_t addr = b1base +
                    sw128((uint32_t)((g2 * 16 + brow) * 128 + q * 32 + bkb));
                ldsm4(bfr[2 * g2][0], bfr[2 * g2][1],
                      bfr[2 * g2 + 1][0], bfr[2 * g2 + 1][1], addr);
            }
            #pragma unroll
            for (int g = 0; g < 8; g++)
                mma16816(acc[g][0], acc[g][1], acc[g][2], acc[g][3],
                         afr[0][q][0], afr[0][q][1], afr[0][q][2], afr[0][q][3],
                         bfr[g][0], bfr[g][1]);
        }

        const float* hnp = (const float*)(smem + SM_HN + buf * 256);
        const int colbase = ci * NTILE + lq;
        tile_top2(acc, 0, 1, hnp, lq, colbase, b1_0, b2_0, i1_0);
        tile_top2(acc, 2, 3, hnp, lq, colbase, b1_1, b2_1, i1_1);

        __syncthreads();
        if (ci + 2 < ci1) { load_tile(ci + 2, buf); CP_COMMIT(); }
    }

    #pragma unroll
    for (int o = 1; o <= 2; o <<= 1) {
        t2_merge_shfl(b1_0, b2_0, i1_0, o);
        t2_merge_shfl(b1_1, b2_1, i1_1, o);
    }

    if ((lane & 3) == 0) {
        int r = w * 16 + (lane >> 2);
        #pragma unroll
        for (int pair = 0; pair < 2; pair++) {
            float pb1 = pair ? b1_1 : b1_0;
            float pb2 = pair ? b2_1 : b2_0;
            int   pi1 = pair ? i1_1 : i1_0;
            int li = blockIdx.x * MTILE + r + pair * 8;
            if (li < nf) {
                g_s2b1[li * NSLICE + slice] = pb1;
                g_s2b2[li * NSLICE + slice] = pb2;
                g_s2i1[li * NSLICE + slice] = pi1;
            }
        }
    }
}

// ---------------------------------------------------------------------------
__global__ __launch_bounds__(256)
void k_resolve() {
    int li = blockIdx.x * 256 + threadIdx.x;
    if (li >= g_nflag) return;
    int t = g_list[li];
    float B1 = -3.4e38f, B2 = -3.4e38f;
    int I1 = 0;
    #pragma unroll
    for (int s = 0; s < NSLICE; s++) {
        float b1 = g_s2b1[li * NSLICE + s];
        float b2 = g_s2b2[li * NSLICE + s];
        int   i1 = g_s2i1[li * NSLICE + s];
        if (b1 > B1) { B2 = fmaxf(B1, b2); B1 = b1; I1 = i1; }
        else { B2 = fmaxf(B2, b1); }
    }
    g_idx[t] = I1;
    if (B1 - B2 < MARGIN2) {
        g_flag2[t] = 1;
        g_key[t] = 0xFFFFFFFFFFFFFFFFULL;
        int slot = atomicAdd(&g_nflag2, 1);
        g_list2[slot] = t;
    }
}

// ---------------------------------------------------------------------------
__global__ __launch_bounds__(256)
void k_refine(const float* __restrict__ z, const float* __restrict__ emb) {
    __shared__ float sx[C_DIM];
    __shared__ u64 rk[8];
    const int tid = threadIdx.x;
    const int lane = tid & 31;
    const int wid = tid >> 5;
    const int nf = g_nflag2;
    if (nf == 0) return;

    for (int wk = blockIdx.x; wk < nf * 64; wk += gridDim.x) {
        const int it = wk >> 6;
        const int slice = wk & 63;
        const int t = g_list2[it];
        __syncthreads();
        if (tid < C_DIM) {
            const float* zp = z + (size_t)(t >> 10) * (C_DIM * HW) + (t & 1023);
            sx[tid] = zp[tid * HW];
        }
        __syncthreads();

        u64 key = 0xFFFFFFFFFFFFFFFFULL;
        if (tid < 128) {
            int k = slice * 128 + tid;
            const float4* e4 = (const float4*)(emb + (size_t)k * C_DIM);
            float s = 0.0f;
            #pragma unroll
            for (int j = 0; j < 16; j++) {
                float4 e = e4[j];
                s += sx[4 * j] * e.x + sx[4 * j + 1] * e.y
                   + sx[4 * j + 2] * e.z + sx[4 * j + 3] * e.w;
            }
            s -= g_hn[k];
            key = ((u64)(~fmono(s)) << 32) | (u32)k;
        }
        #pragma unroll
        for (int o = 16; o > 0; o >>= 1) {
            u64 ok = __shfl_xor_sync(0xffffffffu, key, o);
            if (ok < key) key = ok;
        }
        if (lane == 0) rk[wid] = key;
        __syncthreads();
        if (tid == 0) {
            u64 kmin = rk[0];
            #pragma unroll
            for (int w2 = 1; w2 < 8; w2++) if (rk[w2] < kmin) kmin = rk[w2];
            atomicMin(&g_key[t], kmin);
        }
    }
}

// ---------------------------------------------------------------------------
__global__ __launch_bounds__(256)
void k_epi(const float* __restrict__ z, const float* __restrict__ emb,
           float* __restrict__ out) {
    const int gid = blockIdx.x * blockDim.x + threadIdx.x;
    const int t = gid >> 2;
    const int part = gid & 3;
    if (t >= N_TOK) return;
    const int b = t >> 10;
    const int hw = t & 1023;
    const float* zp = z + (size_t)b * (C_DIM * HW) + hw;

    int bi = g_flag2[t] ? (int)(u32)(g_key[t] & 0xFFFFFFFFULL) : g_idx[t];
    if (part == 0) {
        out[O_IDX + t] = (float)bi;
        atomicAdd(&g_counts[bi], 1.0f);
    }

    const float4* er = (const float4*)(emb + (size_t)bi * C_DIM) + part * 4;
    float* dwp = g_dw + (size_t)bi * C_DIM;
    float* zq   = out + O_ZQ   + (size_t)b * (C_DIM * HW) + hw;
    float* zqst = out + O_ZQST + (size_t)b * (C_DIM * HW) + hw;

    #pragma unroll
    for (int j = 0; j < 4; j++) {
        float4 q = er[j];
        int c = part * 16 + 4 * j;
        float x0 = zp[(c + 0) * HW];
        float x1 = zp[(c + 1) * HW];
        float x2 = zp[(c + 2) * HW];
        float x3 = zp[(c + 3) * HW];
        zq[(c + 0) * HW] = q.x;
        zq[(c + 1) * HW] = q.y;
        zq[(c + 2) * HW] = q.z;
        zq[(c + 3) * HW] = q.w;
        zqst[(c + 0) * HW] = x0 + (q.x - x0);
        zqst[(c + 1) * HW] = x1 + (q.y - x1);
        zqst[(c + 2) * HW] = x2 + (q.z - x2);
        zqst[(c + 3) * HW] = x3 + (q.w - x3);
        atomicAdd(dwp + c + 0, x0);
        atomicAdd(dwp + c + 1, x1);
        atomicAdd(dwp + c + 2, x2);
        atomicAdd(dwp + c + 3, x3);
    }
}

// ---------------------------------------------------------------------------
__global__ __launch_bounds__(256)
void k_cs(const float* __restrict__ cs, float* __restrict__ out) {
    const float OMD = 0.01f;
    int i = blockIdx.x * 256 + threadIdx.x;
    float v = 0.99f * cs[i] + OMD * g_counts[i];
    out[O_CS + i] = v;
    #pragma unroll
    for (int o = 16; o > 0; o >>= 1) v += __shfl_xor_sync(0xffffffffu, v, o);
    __shared__ float red[8];
    if ((threadIdx.x & 31) == 0) red[threadIdx.x >> 5] = v;
    __syncthreads();
    if (threadIdx.x == 0) {
        float s = red[0];
        #pragma unroll
        for (int w2 = 1; w2 < 8; w2++) s += red[w2];
        atomicAdd(&g_n, s);
    }
}

__global__ void k_emb(const float* __restrict__ cs, const float* __restrict__ avg,
                      float* __restrict__ out) {
    const float OMD = 0.01f;
    const float EPSF = 1e-5f;
    int i = blockIdx.x * blockDim.x + threadIdx.x;
    if (i >= K_CODES * C_DIM) return;
    int k = i >> 6;
    float ncs = 0.99f * cs[k] + OMD * g_counts[k];
    float navg = 0.99f * avg[i] + OMD * g_dw[i];
    float n = g_n;
    float denom = (ncs + EPSF) / (n + (float)K_CODES * EPSF) * n;
    out[O_EMB + i] = navg / denom;
    out[O_AVG + i] = navg;
}

// ---------------------------------------------------------------------------
extern "C" void kernel_launch(void* const* d_in, const int* in_sizes, int n_in,
                              void* d_out, int out_size) {
    const float* z   = (const float*)d_in[0];
    const float* emb = (const float*)d_in[1];
    const float* cs  = (const float*)d_in[2];
    const float* avg = (const float*)d_in[3];
    float* out = (float*)d_out;

    cudaFuncSetAttribute(k_dist1, cudaFuncAttributeMaxDynamicSharedMemorySize, SMEM1_TOTAL);
    cudaFuncSetAttribute(k_dist2, cudaFuncAttributeMaxDynamicSharedMemorySize, SMEM2_TOTAL);

    k_initA<<<(K_CODES * C_DIM + 255) / 256, 256>>>();                 // 1
    k_initB<<<(N_TOK + 255) / 256, 256>>>();                           // 2
    k_splitE<<<(K_CODES * 32 + 255) / 256, 256>>>(emb);                // 3
    k_dist1<<<N_TOK / MTILE, TPB, SMEM1_TOTAL>>>(z);                   // 4 <- profiled
    k_pack<<<256, 256>>>(z);                                           // 5
    k_dist2<<<dim3(N_TOK / MTILE, NSLICE), TPB, SMEM2_TOTAL>>>();      // 6
    k_resolve<<<N_TOK / 256, 256>>>();                                 // 7
    k_refine<<<128, 256>>>(z, emb);                                    // 8
    k_epi<<<(4 * N_TOK + 255) / 256, 256>>>(z, emb, out);              // 9
    k_cs<<<K_CODES / 256, 256>>>(cs, out);                             // 10
    k_emb<<<(K_CODES * C_DIM + 255) / 256, 256>>>(cs, avg, out);       // 11
}

// round 12
// speedup vs baseline: 3.2974x; 1.0877x over previous
#include <cuda_runtime.h>
#include <cuda_fp16.h>
#include <cstdint>

#define K_CODES 8192
#define C_DIM   64
#define N_TOK   16384
#define HW      1024
#define TPB     256
#define MTILE   128
#define NTILE   64
#define NTILES  (K_CODES / NTILE)    // 128
#define KSPLIT1 2
#define TPH     (NTILES / KSPLIT1)   // 64 tiles per stage-1 half
#define NSLICE  8
#define TPSLICE (NTILES / NSLICE)    // 16
#define MARGIN1 0.28f                // deterministic 1-term fp16 bound
#define MARGIN2 1e-4f                // proven R5-R8

#define O_ZQST 0
#define O_IDX  1048576
#define O_ZQ   1064960
#define O_EMB  2113536
#define O_CS   2637824
#define O_AVG  2646016

#define SM1_A   0
#define SM1_B   16384
#define SM1_HN  32768
#define SMEM1_TOTAL (32768 + 512 + 128)

#define SM_A    0
#define SM_B    32768
#define SM_HN   65536
#define SMEM2_TOTAL (65536 + 512 + 128)

typedef unsigned long long u64;
typedef unsigned int u32;

static __device__ __half g_Eh[K_CODES * C_DIM];
static __device__ __half g_Er[K_CODES * C_DIM];
static __device__ __half g_Ph[N_TOK * C_DIM];
static __device__ __half g_Pr[N_TOK * C_DIM];
static __device__ float g_hn[K_CODES];
static __device__ int   g_idx[N_TOK];
static __device__ int   g_flag2[N_TOK];
static __device__ u64   g_key[N_TOK];
static __device__ int   g_list[N_TOK];
static __device__ int   g_list2[N_TOK];
static __device__ int   g_nflag;
static __device__ int   g_nflag2;
static __device__ float g_s1b1[N_TOK * KSPLIT1];
static __device__ float g_s1b2[N_TOK * KSPLIT1];
static __device__ int   g_s1i1[N_TOK * KSPLIT1];
static __device__ float g_s2b1[N_TOK * NSLICE];
static __device__ float g_s2b2[N_TOK * NSLICE];
static __device__ int   g_s2i1[N_TOK * NSLICE];
static __device__ float g_counts[K_CODES];
static __device__ float g_dw[K_CODES * C_DIM];
static __device__ float g_n;

// ---------------------------------------------------------------- helpers
__device__ __forceinline__ uint32_t smem_u32(const void* p) {
    uint32_t a;
    asm("{ .reg .u64 t; cvta.to.shared.u64 t, %1; cvt.u32.u64 %0, t; }"
        : "=r"(a) : "l"(p));
    return a;
}
__device__ __forceinline__ void cp_async16(uint32_t saddr, const void* gmem) {
    asm volatile("cp.async.cg.shared.global [%0], [%1], 16;\n" :: "r"(saddr), "l"(gmem));
}
#define CP_COMMIT() asm volatile("cp.async.commit_group;\n" ::: "memory")
#define CP_WAIT(n)  asm volatile("cp.async.wait_group %0;\n" :: "n"(n) : "memory")

__device__ __forceinline__ uint32_t sw128(uint32_t off) {
    return off ^ ((off >> 3) & 0x70);
}
__device__ __forceinline__ void ldsm4(u32& r0, u32& r1, u32& r2, u32& r3, uint32_t addr) {
    asm volatile("ldmatrix.sync.aligned.m8n8.x4.shared.b16 {%0,%1,%2,%3}, [%4];"
                 : "=r"(r0), "=r"(r1), "=r"(r2), "=r"(r3) : "r"(addr));
}
__device__ __forceinline__ void mma16816(float& d0, float& d1, float& d2, float& d3,
                                         u32 a0, u32 a1, u32 a2, u32 a3,
                                         u32 b0, u32 b1) {
    asm volatile("mma.sync.aligned.m16n8k16.row.col.f32.f16.f16.f32 "
                 "{%0,%1,%2,%3}, {%4,%5,%6,%7}, {%8,%9}, {%0,%1,%2,%3};"
                 : "+f"(d0), "+f"(d1), "+f"(d2), "+f"(d3)
                 : "r"(a0), "r"(a1), "r"(a2), "r"(a3), "r"(b0), "r"(b1));
}
__device__ __forceinline__ u32 fmono(float s) {
    u32 u = __float_as_uint(s);
    return (s < 0.0f) ? ~u : (u | 0x80000000u);
}

// branchless top-2 merge; A preferred on tie (A carries smaller indices)
__device__ __forceinline__ void merge2(float& m1a, float& m2a, int& ia,
                                       float m1b, float m2b, int ib) {
    float mn = fminf(m1a, m1b);
    m2a = fmaxf(mn, fmaxf(m2a, m2b));
    ia = (m1a >= m1b) ? ia : ib;
    m1a = fmaxf(m1a, m1b);
}
__device__ __forceinline__ void t2_merge_shfl(float& b1, float& b2, int& i1, int o) {
    float ob1 = __shfl_xor_sync(0xffffffffu, b1, o);
    float ob2 = __shfl_xor_sync(0xffffffffu, b2, o);
    int   oi1 = __shfl_xor_sync(0xffffffffu, i1, o);
    if (ob1 > b1 || (ob1 == b1 && oi1 < i1)) {
        b2 = fmaxf(b1, ob2); b1 = ob1; i1 = oi1;
    } else {
        b2 = fmaxf(b2, ob1);
    }
}
__device__ __forceinline__ void tile_top2(const float acc[8][4], int v0, int v1,
                                          const float* hnp, int lq, int colbase,
                                          float& b1, float& b2, int& i1) {
    float m1[8], m2[8]; int ii[8];
    #pragma unroll
    for (int g = 0; g < 8; g++) {
        int lc = g * 8 + lq;
        float sa = acc[g][v0] - hnp[lc];
        float sb = acc[g][v1] - hnp[lc + 1];
        m1[g] = fmaxf(sa, sb);
        m2[g] = fminf(sa, sb);
        ii[g] = (sa >= sb) ? (colbase + g * 8) : (colbase + g * 8 + 1);
    }
    #pragma unroll
    for (int st = 1; st < 8; st <<= 1)
        #pragma unroll
        for (int g = 0; g < 8; g += 2 * st)
            merge2(m1[g], m2[g], ii[g], m1[g + st], m2[g + st], ii[g + st]);
    merge2(b1, b2, i1, m1[0], m2[0], ii[0]);
}

// ---------------------------------------------------------------------------
__global__ void k_initA() {
    int i = blockIdx.x * blockDim.x + threadIdx.x;
    if (i < K_CODES * C_DIM) g_dw[i] = 0.0f;
}
__global__ void k_initB() {
    int i = blockIdx.x * blockDim.x + threadIdx.x;
    if (i < K_CODES) g_counts[i] = 0.0f;
    if (i < N_TOK) g_flag2[i] = 0;
    if (i == 0) { g_nflag = 0; g_nflag2 = 0; g_n = 0.0f; }
}

__global__ void k_splitE(const float* __restrict__ emb) {
    int w = (blockIdx.x * blockDim.x + threadIdx.x) >> 5;
    int lane = threadIdx.x & 31;
    if (w >= K_CODES) return;
    float s = 0.0f;
    #pragma unroll
    for (int half = 0; half < 2; half++) {
        int c = lane + half * 32;
        float x = emb[w * C_DIM + c];
        s += x * x;
        __half h = __float2half_rn(x);
        float r = x - __half2float(h);
        g_Eh[w * C_DIM + c] = h;
        g_Er[w * C_DIM + c] = __float2half_rn(r);
    }
    #pragma unroll
    for (int o = 16; o > 0; o >>= 1) s += __shfl_xor_sync(0xffffffffu, s, o);
    if (lane == 0) g_hn[w] = 0.5f * s;
}

// ---------------------------------------------------------------------------
// STAGE 1: coarse scores (hh only) over one K-half; per-half top-2 to tables.
// grid = (128 token-tiles, 2 K-halves); 2 CTAs/SM.   [captured launch #4]
__global__ void __launch_bounds__(TPB, 2) k_dist1(const float* __restrict__ z) {
    extern __shared__ char smem[];
    const uint32_t sb = smem_u32(smem);
    const int tid = threadIdx.x;
    const int lane = tid & 31;
    const int w = tid >> 5;
    const int half_k = blockIdx.y;
    const int ci0 = half_k * TPH;
    const int ci1 = ci0 + TPH;

    {
        int r = tid & 127;
        int half = tid >> 7;
        int t = blockIdx.x * MTILE + r;
        const float* zp = z + (size_t)(t >> 10) * (C_DIM * HW) + (t & 1023);
        #pragma unroll
        for (int j = 0; j < 32; j++) {
            int c = half * 32 + j;
            uint32_t off = sw128((uint32_t)(r * 128 + c * 2));
            *(__half*)(smem + SM1_A + off) = __float2half_rn(zp[c * HW]);
        }
    }
    __syncthreads();

    u32 afr[4][4];
    {
        int arow = w * 16 + (lane & 7) + ((lane >> 3) & 1) * 8;
        int akb  = (lane >> 4) * 16;
        #pragma unroll
        for (int q = 0; q < 4; q++) {
            uint32_t addr = sb + SM1_A + sw128((uint32_t)(arow * 128 + q * 32 + akb));
            ldsm4(afr[q][0], afr[q][1], afr[q][2], afr[q][3], addr);
        }
    }

    auto load_tile = [&](int tile, int bufi) {
        const char* src = (const char*)g_Eh + (size_t)tile * (NTILE * C_DIM * 2);
        uint32_t dst = sb + SM1_B + (uint32_t)bufi * 8192u;
        #pragma unroll
        for (int u = 0; u < 2; u++) {
            uint32_t off = (uint32_t)(u * TPB + tid) * 16u;
            cp_async16(dst + sw128(off), src + off);
        }
        if (tid < 16)
            cp_async16(sb + SM1_HN + bufi * 256 + tid * 16,
                       (const char*)(g_hn + tile * NTILE) + tid * 16);
    };

    const int brow = (lane & 7) + ((lane >> 4) & 1) * 8;
    const int bkb  = ((lane >> 3) & 1) * 16;
    const int lq   = 2 * (lane & 3);

    float b1_0 = -3.4e38f, b2_0 = -3.4e38f;
    float b1_1 = -3.4e38f, b2_1 = -3.4e38f;
    int i1_0 = 0, i1_1 = 0;

    load_tile(ci0, 0); CP_COMMIT();
    load_tile(ci0 + 1, 1); CP_COMMIT();

    for (int ci = ci0; ci < ci1; ci++) {
        const int buf = ci & 1;
        if (ci + 1 < ci1) { CP_WAIT(1); } else { CP_WAIT(0); }
        __syncthreads();

        float acc[8][4];
        #pragma unroll
        for (int g = 0; g < 8; g++)
            #pragma unroll
            for (int v = 0; v < 4; v++) acc[g][v] = 0.0f;

        uint32_t bbase = sb + SM1_B + (uint32_t)buf * 8192u;
        #pragma unroll
        for (int q = 0; q < 4; q++) {
            u32 bfr[8][2];
            #pragma unroll
            for (int g2 = 0; g2 < 4; g2++) {
                uint32_t addr = bbase +
                    sw128((uint32_t)((g2 * 16 + brow) * 128 + q * 32 + bkb));
                ldsm4(bfr[2 * g2][0], bfr[2 * g2][1],
                      bfr[2 * g2 + 1][0], bfr[2 * g2 + 1][1], addr);
            }
            #pragma unroll
            for (int g = 0; g < 8; g++)
                mma16816(acc[g][0], acc[g][1], acc[g][2], acc[g][3],
                         afr[q][0], afr[q][1], afr[q][2], afr[q][3],
                         bfr[g][0], bfr[g][1]);
        }

        const float* hnp = (const float*)(smem + SM1_HN + buf * 256);
        const int colbase = ci * NTILE + lq;
        tile_top2(acc, 0, 1, hnp, lq, colbase, b1_0, b2_0, i1_0);
        tile_top2(acc, 2, 3, hnp, lq, colbase, b1_1, b2_1, i1_1);

        __syncthreads();
        if (ci + 2 < ci1) { load_tile(ci + 2, buf); CP_COMMIT(); }
    }

    #pragma unroll
    for (int o = 1; o <= 2; o <<= 1) {
        t2_merge_shfl(b1_0, b2_0, i1_0, o);
        t2_merge_shfl(b1_1, b2_1, i1_1, o);
    }

    if ((lane & 3) == 0) {
        int r = w * 16 + (lane >> 2);
        int tt = blockIdx.x * MTILE + r;
        g_s1b1[tt * KSPLIT1 + half_k] = b1_0;
        g_s1b2[tt * KSPLIT1 + half_k] = b2_0;
        g_s1i1[tt * KSPLIT1 + half_k] = i1_0;
        g_s1b1[(tt + 8) * KSPLIT1 + half_k] = b1_1;
        g_s1b2[(tt + 8) * KSPLIT1 + half_k] = b2_1;
        g_s1i1[(tt + 8) * KSPLIT1 + half_k] = i1_1;
    }
}

// merge stage-1 halves; set g_idx; flag gap < MARGIN1
__global__ __launch_bounds__(256)
void k_resolve1() {
    int t = blockIdx.x * 256 + threadIdx.x;
    if (t >= N_TOK) return;
    float B1 = g_s1b1[t * KSPLIT1];
    float B2 = g_s1b2[t * KSPLIT1];
    int   I1 = g_s1i1[t * KSPLIT1];
    #pragma unroll
    for (int s = 1; s < KSPLIT1; s++) {
        float b1 = g_s1b1[t * KSPLIT1 + s];
        float b2 = g_s1b2[t * KSPLIT1 + s];
        int   i1 = g_s1i1[t * KSPLIT1 + s];
        if (b1 > B1) { B2 = fmaxf(B1, b2); B1 = b1; I1 = i1; }
        else { B2 = fmaxf(B2, b1); }
    }
    g_idx[t] = I1;
    if (B1 - B2 < MARGIN1) {
        int slot = atomicAdd(&g_nflag, 1);
        g_list[slot] = t;
    }
}

// ---------------------------------------------------------------------------
__global__ __launch_bounds__(256)
void k_pack(const float* __restrict__ z) {
    int nf = g_nflag;
    int total = nf * C_DIM;
    for (int i = blockIdx.x * 256 + threadIdx.x; i < total; i += gridDim.x * 256) {
        int li = i >> 6, c = i & 63;
        int t = g_list[li];
        float x = z[(size_t)(t >> 10) * (C_DIM * HW) + c * HW + (t & 1023)];
        __half h = __float2half_rn(x);
        g_Ph[i] = h;
        g_Pr[i] = __float2half_rn(x - __half2float(h));
    }
}

// ---------------------------------------------------------------------------
// STAGE 2: 3-term scores for flagged tokens over one K-slice (16 tiles).
__global__ void __launch_bounds__(TPB, 1) k_dist2() {
    const int nf = g_nflag;
    if ((int)blockIdx.x * MTILE >= nf) return;

    extern __shared__ char smem[];
    const uint32_t sb = smem_u32(smem);
    const int tid = threadIdx.x;
    const int lane = tid & 31;
    const int w = tid >> 5;
    const int slice = blockIdx.y;
    const int ci0 = slice * TPSLICE;
    const int ci1 = ci0 + TPSLICE;

    {
        int r = tid & 127;
        int half = tid >> 7;
        int li = blockIdx.x * MTILE + r;
        size_t rowo = (size_t)((li < nf) ? li : 0) * C_DIM;
        const uint4* srch = (const uint4*)(g_Ph + rowo);
        const uint4* srcr = (const uint4*)(g_Pr + rowo);
        #pragma unroll
        for (int j = 0; j < 4; j++) {
            int chunk = half * 4 + j;
            uint32_t off = sw128((uint32_t)(r * 128 + chunk * 16));
            *(uint4*)(smem + SM_A + off) = srch[chunk];
            *(uint4*)(smem + SM_A + 16384 + off) = srcr[chunk];
        }
    }
    __syncthreads();

    u32 afr[2][4][4];
    {
        int arow = w * 16 + (lane & 7) + ((lane >> 3) & 1) * 8;
        int akb  = (lane >> 4) * 16;
        #pragma unroll
        for (int c = 0; c < 2; c++)
            #pragma unroll
            for (int q = 0; q < 4; q++) {
                uint32_t addr = sb + SM_A + c * 16384 +
                                sw128((uint32_t)(arow * 128 + q * 32 + akb));
                ldsm4(afr[c][q][0], afr[c][q][1], afr[c][q][2], afr[c][q][3], addr);
            }
    }

    auto load_tile = [&](int tile, int bufi) {
        const char* srcs[2] = {(const char*)g_Eh, (const char*)g_Er};
        #pragma unroll
        for (int c = 0; c < 2; c++) {
            const char* src = srcs[c] + (size_t)tile * (NTILE * C_DIM * 2);
            uint32_t dst = sb + SM_B + (uint32_t)(bufi * 2 + c) * 8192u;
            #pragma unroll
            for (int u = 0; u < 2; u++) {
                uint32_t off = (uint32_t)(u * TPB + tid) * 16u;
                cp_async16(dst + sw128(off), src + off);
            }
        }
        if (tid < 16)
            cp_async16(sb + SM_HN + bufi * 256 + tid * 16,
                       (const char*)(g_hn + tile * NTILE) + tid * 16);
    };

    const int brow = (lane & 7) + ((lane >> 4) & 1) * 8;
    const int bkb  = ((lane >> 3) & 1) * 16;
    const int lq   = 2 * (lane & 3);

    float b1_0 = -3.4e38f, b2_0 = -3.4e38f;
    float b1_1 = -3.4e38f, b2_1 = -3.4e38f;
    int i1_0 = 0, i1_1 = 0;

    load_tile(ci0, 0); CP_COMMIT();
    load_tile(ci0 + 1, 1); CP_COMMIT();

    for (int ci = ci0; ci < ci1; ci++) {
        const int buf = ci & 1;
        if (ci + 1 < ci1) { CP_WAIT(1); } else { CP_WAIT(0); }
        __syncthreads();

        float acc[8][4];
        #pragma unroll
        for (int g = 0; g < 8; g++)
            #pragma unroll
            for (int v = 0; v < 4; v++) acc[g][v] = 0.0f;

        #pragma unroll
        for (int q = 0; q < 4; q++) {
            u32 bfr[8][2];
            uint32_t b0base = sb + SM_B + (uint32_t)(buf * 2) * 8192u;
            #pragma unroll
            for (int g2 = 0; g2 < 4; g2++) {
                uint32_t addr = b0base +
                    sw128((uint32_t)((g2 * 16 + brow) * 128 + q * 32 + bkb));
                ldsm4(bfr[2 * g2][0], bfr[2 * g2][1],
                      bfr[2 * g2 + 1][0], bfr[2 * g2 + 1][1], addr);
            }
            #pragma unroll
            for (int g = 0; g < 8; g++) {
                mma16816(acc[g][0], acc[g][1], acc[g][2], acc[g][3],
                         afr[0][q][0], afr[0][q][1], afr[0][q][2], afr[0][q][3],
                         bfr[g][0], bfr[g][1]);
                mma16816(acc[g][0], acc[g][1], acc[g][2], acc[g][3],
                         afr[1][q][0], afr[1][q][1], afr[1][q][2], afr[1][q][3],
                         bfr[g][0], bfr[g][1]);
            }
            uint32_t b1base = sb + SM_B + (uint32_t)(buf * 2 + 1) * 8192u;
            #pragma unroll
            for (int g2 = 0; g2 < 4; g2++) {
                uint32_t addr = b1base +
                    sw128((uint32_t)((g2 * 16 + brow) * 128 + q * 32 + bkb));
                ldsm4(bfr[2 * g2][0], bfr[2 * g2][1],
                      bfr[2 * g2 + 1][0], bfr[2 * g2 + 1][1], addr);
            }
            #pragma unroll
            for (int g = 0; g < 8; g++)
                mma16816(acc[g][0], acc[g][1], acc[g][2], acc[g][3],
                         afr[0][q][0], afr[0][q][1], afr[0][q][2], afr[0][q][3],
                         bfr[g][0], bfr[g][1]);
        }

        const float* hnp = (const float*)(smem + SM_HN + buf * 256);
        const int colbase = ci * NTILE + lq;
        tile_top2(acc, 0, 1, hnp, lq, colbase, b1_0, b2_0, i1_0);
        tile_top2(acc, 2, 3, hnp, lq, colbase, b1_1, b2_1, i1_1);

        __syncthreads();
        if (ci + 2 < ci1) { load_tile(ci + 2, buf); CP_COMMIT(); }
    }

    #pragma unroll
    for (int o = 1; o <= 2; o <<= 1) {
        t2_merge_shfl(b1_0, b2_0, i1_0, o);
        t2_merge_shfl(b1_1, b2_1, i1_1, o);
    }

    if ((lane & 3) == 0) {
        int r = w * 16 + (lane >> 2);
        #pragma unroll
        for (int pair = 0; pair < 2; pair++) {
            float pb1 = pair ? b1_1 : b1_0;
            float pb2 = pair ? b2_1 : b2_0;
            int   pi1 = pair ? i1_1 : i1_0;
            int li = blockIdx.x * MTILE + r + pair * 8;
            if (li < nf) {
                g_s2b1[li * NSLICE + slice] = pb1;
                g_s2b2[li * NSLICE + slice] = pb2;
                g_s2i1[li * NSLICE + slice] = pi1;
            }
        }
    }
}

// ---------------------------------------------------------------------------
__global__ __launch_bounds__(256)
void k_resolve2() {
    int li = blockIdx.x * 256 + threadIdx.x;
    if (li >= g_nflag) return;
    int t = g_list[li];
    float B1 = -3.4e38f, B2 = -3.4e38f;
    int I1 = 0;
    #pragma unroll
    for (int s = 0; s < NSLICE; s++) {
        float b1 = g_s2b1[li * NSLICE + s];
        float b2 = g_s2b2[li * NSLICE + s];
        int   i1 = g_s2i1[li * NSLICE + s];
        if (b1 > B1) { B2 = fmaxf(B1, b2); B1 = b1; I1 = i1; }
        else { B2 = fmaxf(B2, b1); }
    }
    g_idx[t] = I1;
    if (B1 - B2 < MARGIN2) {
        g_flag2[t] = 1;
        g_key[t] = 0xFFFFFFFFFFFFFFFFULL;
        int slot = atomicAdd(&g_nflag2, 1);
        g_list2[slot] = t;
    }
}

// ---------------------------------------------------------------------------
__global__ __launch_bounds__(256)
void k_refine(const float* __restrict__ z, const float* __restrict__ emb) {
    __shared__ float sx[C_DIM];
    __shared__ u64 rk[8];
    const int tid = threadIdx.x;
    const int lane = tid & 31;
    const int wid = tid >> 5;
    const int nf = g_nflag2;
    if (nf == 0) return;

    for (int wk = blockIdx.x; wk < nf * 64; wk += gridDim.x) {
        const int it = wk >> 6;
        const int slice = wk & 63;
        const int t = g_list2[it];
        __syncthreads();
        if (tid < C_DIM) {
            const float* zp = z + (size_t)(t >> 10) * (C_DIM * HW) + (t & 1023);
            sx[tid] = zp[tid * HW];
        }
        __syncthreads();

        u64 key = 0xFFFFFFFFFFFFFFFFULL;
        if (tid < 128) {
            int k = slice * 128 + tid;
            const float4* e4 = (const float4*)(emb + (size_t)k * C_DIM);
            float s = 0.0f;
            #pragma unroll
            for (int j = 0; j < 16; j++) {
                float4 e = e4[j];
                s += sx[4 * j] * e.x + sx[4 * j + 1] * e.y
                   + sx[4 * j + 2] * e.z + sx[4 * j + 3] * e.w;
            }
            s -= g_hn[k];
            key = ((u64)(~fmono(s)) << 32) | (u32)k;
        }
        #pragma unroll
        for (int o = 16; o > 0; o >>= 1) {
            u64 ok = __shfl_xor_sync(0xffffffffu, key, o);
            if (ok < key) key = ok;
        }
        if (lane == 0) rk[wid] = key;
        __syncthreads();
        if (tid == 0) {
            u64 kmin = rk[0];
            #pragma unroll
            for (int w2 = 1; w2 < 8; w2++) if (rk[w2] < kmin) kmin = rk[w2];
            atomicMin(&g_key[t], kmin);
        }
    }
}

// ---------------------------------------------------------------------------
__global__ __launch_bounds__(256)
void k_epi(const float* __restrict__ z, const float* __restrict__ emb,
           float* __restrict__ out) {
    const int gid = blockIdx.x * blockDim.x + threadIdx.x;
    const int t = gid >> 2;
    const int part = gid & 3;
    if (t >= N_TOK) return;
    const int b = t >> 10;
    const int hw = t & 1023;
    const float* zp = z + (size_t)b * (C_DIM * HW) + hw;

    int bi = g_flag2[t] ? (int)(u32)(g_key[t] & 0xFFFFFFFFULL) : g_idx[t];
    if (part == 0) {
        out[O_IDX + t] = (float)bi;
        atomicAdd(&g_counts[bi], 1.0f);
    }

    const float4* er = (const float4*)(emb + (size_t)bi * C_DIM) + part * 4;
    float* dwp = g_dw + (size_t)bi * C_DIM;
    float* zq   = out + O_ZQ   + (size_t)b * (C_DIM * HW) + hw;
    float* zqst = out + O_ZQST + (size_t)b * (C_DIM * HW) + hw;

    #pragma unroll
    for (int j = 0; j < 4; j++) {
        float4 q = er[j];
        int c = part * 16 + 4 * j;
        float x0 = zp[(c + 0) * HW];
        float x1 = zp[(c + 1) * HW];
        float x2 = zp[(c + 2) * HW];
        float x3 = zp[(c + 3) * HW];
        zq[(c + 0) * HW] = q.x;
        zq[(c + 1) * HW] = q.y;
        zq[(c + 2) * HW] = q.z;
        zq[(c + 3) * HW] = q.w;
        zqst[(c + 0) * HW] = x0 + (q.x - x0);
        zqst[(c + 1) * HW] = x1 + (q.y - x1);
        zqst[(c + 2) * HW] = x2 + (q.z - x2);
        zqst[(c + 3) * HW] = x3 + (q.w - x3);
        atomicAdd(dwp + c + 0, x0);
        atomicAdd(dwp + c + 1, x1);
        atomicAdd(dwp + c + 2, x2);
        atomicAdd(dwp + c + 3, x3);
    }
}

// ---------------------------------------------------------------------------
__global__ __launch_bounds__(256)
void k_cs(const float* __restrict__ cs, float* __restrict__ out) {
    const float OMD = 0.01f;
    int i = blockIdx.x * 256 + threadIdx.x;
    float v = 0.99f * cs[i] + OMD * g_counts[i];
    out[O_CS + i] = v;
    #pragma unroll
    for (int o = 16; o > 0; o >>= 1) v += __shfl_xor_sync(0xffffffffu, v, o);
    __shared__ float red[8];
    if ((threadIdx.x & 31) == 0) red[threadIdx.x >> 5] = v;
    __syncthreads();
    if (threadIdx.x == 0) {
        float s = red[0];
        #pragma unroll
        for (int w2 = 1; w2 < 8; w2++) s += red[w2];
        atomicAdd(&g_n, s);
    }
}

__global__ void k_emb(const float* __restrict__ cs, const float* __restrict__ avg,
                      float* __restrict__ out) {
    const float OMD = 0.01f;
    const float EPSF = 1e-5f;
    int i = blockIdx.x * blockDim.x + threadIdx.x;
    if (i >= K_CODES * C_DIM) return;
    int k = i >> 6;
    float ncs = 0.99f * cs[k] + OMD * g_counts[k];
    float navg = 0.99f * avg[i] + OMD * g_dw[i];
    float n = g_n;
    float denom = (ncs + EPSF) / (n + (float)K_CODES * EPSF) * n;
    out[O_EMB + i] = navg / denom;
    out[O_AVG + i] = navg;
}

// ---------------------------------------------------------------------------
extern "C" void kernel_launch(void* const* d_in, const int* in_sizes, int n_in,
                              void* d_out, int out_size) {
    const float* z   = (const float*)d_in[0];
    const float* emb = (const float*)d_in[1];
    const float* cs  = (const float*)d_in[2];
    const float* avg = (const float*)d_in[3];
    float* out = (float*)d_out;

    cudaFuncSetAttribute(k_dist1, cudaFuncAttributeMaxDynamicSharedMemorySize, SMEM1_TOTAL);
    cudaFuncSetAttribute(k_dist2, cudaFuncAttributeMaxDynamicSharedMemorySize, SMEM2_TOTAL);

    k_initA<<<(K_CODES * C_DIM + 255) / 256, 256>>>();                     // 1
    k_initB<<<(N_TOK + 255) / 256, 256>>>();                               // 2
    k_splitE<<<(K_CODES * 32 + 255) / 256, 256>>>(emb);                    // 3
    k_dist1<<<dim3(N_TOK / MTILE, KSPLIT1), TPB, SMEM1_TOTAL>>>(z);        // 4 <- profiled
    k_resolve1<<<N_TOK / 256, 256>>>();                                    // 5
    k_pack<<<256, 256>>>(z);                                               // 6
    k_dist2<<<dim3(N_TOK / MTILE, NSLICE), TPB, SMEM2_TOTAL>>>();          // 7
    k_resolve2<<<N_TOK / 256, 256>>>();                                    // 8
    k_refine<<<128, 256>>>(z, emb);                                        // 9
    k_epi<<<(4 * N_TOK + 255) / 256, 256>>>(z, emb, out);                  // 10
    k_cs<<<K_CODES / 256, 256>>>(cs, out);                                 // 11
    k_emb<<<(K_CODES * C_DIM + 255) / 256, 256>>>(cs, avg, out);           // 12
}